// round 11
// baseline (speedup 1.0000x reference)
#include <cuda_runtime.h>
#include <cuda_bf16.h>
#include <cstdint>

#define NN      100000
#define NE      1600000
#define F       128
#define NREL    5
#define NN_PAD  100096          // 782 * 128
#define KTOT    768
#define BLAYER  98304           // 128 * 768 per-layer B elements
#define M5      (NN * NREL)
#define CSR_NB  120             // resident blocks for software grid sync

#if defined(__CUDA_ARCH_FEAT_SM103_ALL) || defined(__CUDA_ARCH_FEAT_SM100_ALL)
#define HAS_TCGEN05 1
#else
#define HAS_TCGEN05 0
#endif

// ---------------- device scratch (no allocations allowed) ----------------
// AG layout: [rel][node][512B block] = 128 bf16 hi (256B) then 128 bf16 lo (256B)
__device__ __align__(256) unsigned char g_AG[(size_t)NREL * NN_PAD * 512];
__device__ __align__(256) __nv_bfloat16 g_Bh[3 * BLAYER];   // weights hi [l][n][k]
__device__ __align__(256) __nv_bfloat16 g_Bl[3 * BLAYER];
__device__ float g_B1[(size_t)NN * F];
__device__ float g_B2[(size_t)NN * F];
__device__ int   g_deg5[M5];
__device__ int   g_off5[M5 + 1];
__device__ int   g_cur5[M5];
__device__ int   g_edges[NE];                 // src, sorted by (dst, rel)
__device__ int   g_bsums[512];
__device__ int   g_bar = 0;
__device__ volatile unsigned g_sense = 0;

// ---------------- small helpers ----------------
__device__ __forceinline__ uint32_t s2u(const void* p) {
    return (uint32_t)__cvta_generic_to_shared(p);
}
__device__ __forceinline__ void bsplit(float v, __nv_bfloat16& h, __nv_bfloat16& l) {
    h = __float2bfloat16_rn(v);
    l = __float2bfloat16_rn(v - __bfloat162float(h));
}
__device__ __forceinline__ void pack8(const float* f, uint4& hi, uint4& lo) {
    uint32_t h[4], l[4];
#pragma unroll
    for (int i = 0; i < 4; i++) {
        __nv_bfloat16 h0, l0, h1, l1;
        bsplit(f[2 * i], h0, l0);
        bsplit(f[2 * i + 1], h1, l1);
        __nv_bfloat162 hh = __halves2bfloat162(h0, h1);
        __nv_bfloat162 ll = __halves2bfloat162(l0, l1);
        h[i] = *(uint32_t*)&hh;
        l[i] = *(uint32_t*)&ll;
    }
    hi = make_uint4(h[0], h[1], h[2], h[3]);
    lo = make_uint4(l[0], l[1], l[2], l[3]);
}
__device__ __forceinline__ void mbar_init(uint32_t a, uint32_t cnt) {
    asm volatile("mbarrier.init.shared.b64 [%0], %1;" :: "r"(a), "r"(cnt) : "memory");
}
__device__ __forceinline__ void mbar_wait(uint32_t a, int par) {
    asm volatile(
        "{\n\t.reg .pred P;\n"
        "WL%=:\n\t"
        "mbarrier.try_wait.parity.acquire.cta.shared::cta.b64 P, [%0], %1, 0x989680;\n\t"
        "@P bra WD%=;\n\t"
        "bra WL%=;\n"
        "WD%=:\n\t}"
        :: "r"(a), "r"(par) : "memory");
}
__device__ __forceinline__ void gsync(int nb) {
    __syncthreads();
    if (threadIdx.x == 0) {
        unsigned s = g_sense;
        __threadfence();
        if (atomicAdd(&g_bar, 1) == nb - 1) {
            g_bar = 0;
            __threadfence();
            g_sense = s + 1;
        } else {
            while (g_sense == s) { }
        }
        __threadfence();
    }
    __syncthreads();
}

// ---------------- single-kernel CSR build: zero -> hist -> scan -> place ----------------
__global__ void __launch_bounds__(1024, 1) k_csr(
    const int* __restrict__ src, const int* __restrict__ dst,
    const int* __restrict__ et, int E, int m)
{
    const int NB = gridDim.x;
    int tid = threadIdx.x, bid = blockIdx.x;
    int gt = bid * 1024 + tid, gs = NB * 1024;
    __shared__ int sh[1024];

    for (int i = gt; i < m; i += gs) g_deg5[i] = 0;
    // zero AG rows for padded nodes (n..NN_PAD) so last-tile MMA reads zeros
    for (int r = 0; r < NREL; r++) {
        unsigned char* p = g_AG + ((size_t)r * NN_PAD + NN) * 512;
        size_t bytes = (size_t)(NN_PAD - NN) * 512;
        for (size_t i = (size_t)gt * 16; i + 16 <= bytes; i += (size_t)gs * 16)
            *(uint4*)(p + i) = make_uint4(0, 0, 0, 0);
    }
    gsync(NB);

    for (int e = gt; e < E; e += gs) atomicAdd(&g_deg5[dst[e] * NREL + et[e]], 1);
    gsync(NB);

    int RB = (m + NB - 1) / NB;
    int CH = (RB + 1023) / 1024;
    int base = bid * RB;
    int lim = min(base + RB, m);
    int i0 = base + tid * CH;
    int mysum = 0;
#pragma unroll 4
    for (int j = 0; j < CH; j++) {
        int i = i0 + j;
        if (i < lim) mysum += g_deg5[i];
    }
    sh[tid] = mysum;
    __syncthreads();
    for (int d = 1; d < 1024; d <<= 1) {
        int t = (tid >= d) ? sh[tid - d] : 0;
        __syncthreads();
        sh[tid] += t;
        __syncthreads();
    }
    if (tid == 1023) g_bsums[bid] = sh[1023];
    int myoff_local = sh[tid] - mysum;
    gsync(NB);

    if (bid == 0) {
        int v = (tid < NB) ? g_bsums[tid] : 0;
        sh[tid] = v;
        __syncthreads();
        for (int d = 1; d < 1024; d <<= 1) {
            int t = (tid >= d) ? sh[tid - d] : 0;
            __syncthreads();
            sh[tid] += t;
            __syncthreads();
        }
        if (tid < NB) g_bsums[tid] = sh[tid] - v;
    }
    gsync(NB);

    int run = g_bsums[bid] + myoff_local;
#pragma unroll 4
    for (int j = 0; j < CH; j++) {
        int i = i0 + j;
        if (i < lim) {
            g_off5[i] = run;
            g_cur5[i] = run;
            run += g_deg5[i];
        }
    }
    if (gt == 0) g_off5[m] = E;
    gsync(NB);

    for (int e = gt; e < E; e += gs) {
        int b = dst[e] * NREL + et[e];
        int pos = atomicAdd(&g_cur5[b], 1);
        g_edges[pos] = src[e];
    }
}

// ---------------- weights -> transposed bf16 hi/lo B matrices ----------------
__global__ void k_prepB(const float* __restrict__ W1, const float* __restrict__ r1,
                        const float* __restrict__ W2, const float* __restrict__ r2,
                        const float* __restrict__ W3, const float* __restrict__ r3) {
    int idx = blockIdx.x * blockDim.x + threadIdx.x;
    if (idx >= 3 * BLAYER) return;
    int l = idx / BLAYER;
    int rem = idx % BLAYER;
    int nn = rem / KTOT;
    int k = rem % KTOT;
    const float* Wl = (l == 0) ? W1 : ((l == 1) ? W2 : W3);
    const float* rl = (l == 0) ? r1 : ((l == 1) ? r2 : r3);
    float v = (k < 128) ? rl[k * 128 + nn] : Wl[(size_t)(k - 128) * 128 + nn];
    __nv_bfloat16 h, lo;
    bsplit(v, h, lo);
    g_Bh[idx] = h;
    g_Bl[idx] = lo;
}

// ---------------- gather: one warp per (node, rel) bucket, always MLP-4 ----------------
__global__ void k_gather(const float* __restrict__ X, int n) {
    int b = (blockIdx.x * blockDim.x + threadIdx.x) >> 5;
    if (b >= n * NREL) return;
    int lane = threadIdx.x & 31;
    int beg = g_off5[b], end = g_off5[b + 1];
    int node = b / NREL, rel = b - node * NREL;
    int cnt = end - beg;

    float ax = 0.f, ay = 0.f, az = 0.f, aw = 0.f;
    // all edges go through a 4-wide path: clamped indices + 0/1 masks keep MLP=4
    for (int e = beg; e < end; e += 4) {
        int i1 = min(e + 1, end - 1);
        int i2 = min(e + 2, end - 1);
        int i3 = min(e + 3, end - 1);
        float m1 = (e + 1 < end) ? 1.f : 0.f;
        float m2 = (e + 2 < end) ? 1.f : 0.f;
        float m3 = (e + 3 < end) ? 1.f : 0.f;
        int s0 = __ldg(&g_edges[e]);
        int s1 = __ldg(&g_edges[i1]);
        int s2 = __ldg(&g_edges[i2]);
        int s3 = __ldg(&g_edges[i3]);
        float4 v0 = __ldg((const float4*)X + (size_t)s0 * 32 + lane);
        float4 v1 = __ldg((const float4*)X + (size_t)s1 * 32 + lane);
        float4 v2 = __ldg((const float4*)X + (size_t)s2 * 32 + lane);
        float4 v3 = __ldg((const float4*)X + (size_t)s3 * 32 + lane);
        ax += (v0.x + m1 * v1.x) + (m2 * v2.x + m3 * v3.x);
        ay += (v0.y + m1 * v1.y) + (m2 * v2.y + m3 * v3.y);
        az += (v0.z + m1 * v1.z) + (m2 * v2.z + m3 * v3.z);
        aw += (v0.w + m1 * v1.w) + (m2 * v2.w + m3 * v3.w);
    }
    float sc = cnt ? 1.f / (float)cnt : 0.f;
    float f0 = ax * sc, f1 = ay * sc, f2 = az * sc, f3 = aw * sc;

    __nv_bfloat16 h0, l0, h1, l1, h2, l2, h3, l3;
    bsplit(f0, h0, l0); bsplit(f1, h1, l1);
    bsplit(f2, h2, l2); bsplit(f3, h3, l3);
    __nv_bfloat162 hA = __halves2bfloat162(h0, h1);
    __nv_bfloat162 hB = __halves2bfloat162(h2, h3);
    __nv_bfloat162 lA = __halves2bfloat162(l0, l1);
    __nv_bfloat162 lB = __halves2bfloat162(l2, l3);
    // contiguous 512B block per bucket: hi[256B] | lo[256B]
    unsigned char* base = g_AG + ((size_t)rel * NN_PAD + node) * 512;
    *(uint2*)(base + lane * 8)       = make_uint2(*(uint32_t*)&hA, *(uint32_t*)&hB);
    *(uint2*)(base + 256 + lane * 8) = make_uint2(*(uint32_t*)&lA, *(uint32_t*)&lB);
}

// ---------------- tcgen05 fused GEMM ----------------
// Y = relu([X | A0..A4] @ Bt + bias), 3-term bf16 split.
// 24 K-chunks of 32; SW64 tiles (128 rows x 64B); 3 stages of 32KB -> 2 CTAs/SM.
#define SMEM_TILES  1024
#define STAGE_BYTES 32768       // Ah(8K) Al(8K) Bh(8K) Bl(8K)
#define SMEM_TOTAL  (SMEM_TILES + 3 * STAGE_BYTES)
#define NCHUNK      24
#define MMA_IDESC   ((1u << 4) | (1u << 7) | (1u << 10) | (16u << 17) | (8u << 24))

#if HAS_TCGEN05
__device__ __forceinline__ uint64_t sdesc64(uint32_t a) {
    // SW64 (layout=4), version=1 (Blackwell), SBO=32, LBO=1 (K-major, 64B rows)
    return ((uint64_t)4 << 61) | ((uint64_t)1 << 46) | ((uint64_t)32 << 32) |
           ((uint64_t)1 << 16) | (uint64_t)((a >> 4) & 0x3FFF);
}
__device__ __forceinline__ void mma_f16_ss(uint32_t d, uint64_t ad, uint64_t bd,
                                           uint32_t idesc, uint32_t en) {
    asm volatile(
        "{\n\t.reg .pred p;\n\t"
        "setp.ne.u32 p, %4, 0;\n\t"
        "tcgen05.mma.cta_group::1.kind::f16 [%0], %1, %2, %3, {%5, %5, %5, %5}, p;\n\t}"
        :: "r"(d), "l"(ad), "l"(bd), "r"(idesc), "r"(en), "r"(0u) : "memory");
}
__device__ __forceinline__ void mma_commit(uint32_t mbar) {
    asm volatile(
        "tcgen05.commit.cta_group::1.mbarrier::arrive::one.shared::cluster.b64 [%0];"
        :: "r"(mbar) : "memory");
}
#define LDTM_X32(r, addr)                                                        \
    asm volatile(                                                                \
        "tcgen05.ld.sync.aligned.32x32b.x32.b32 "                                \
        "{%0, %1, %2, %3, %4, %5, %6, %7, "                                      \
        " %8, %9, %10, %11, %12, %13, %14, %15, "                                \
        " %16, %17, %18, %19, %20, %21, %22, %23, "                              \
        " %24, %25, %26, %27, %28, %29, %30, %31}, [%32];"                       \
        : "=r"((r)[0]),  "=r"((r)[1]),  "=r"((r)[2]),  "=r"((r)[3]),             \
          "=r"((r)[4]),  "=r"((r)[5]),  "=r"((r)[6]),  "=r"((r)[7]),             \
          "=r"((r)[8]),  "=r"((r)[9]),  "=r"((r)[10]), "=r"((r)[11]),            \
          "=r"((r)[12]), "=r"((r)[13]), "=r"((r)[14]), "=r"((r)[15]),            \
          "=r"((r)[16]), "=r"((r)[17]), "=r"((r)[18]), "=r"((r)[19]),            \
          "=r"((r)[20]), "=r"((r)[21]), "=r"((r)[22]), "=r"((r)[23]),            \
          "=r"((r)[24]), "=r"((r)[25]), "=r"((r)[26]), "=r"((r)[27]),            \
          "=r"((r)[28]), "=r"((r)[29]), "=r"((r)[30]), "=r"((r)[31])             \
        : "r"(addr))

// chunks 0..3: A from f32 X (LDG+split+STS), B via cp.async.
// chunks 4..23: A from AG: rel=(c-4)>>2, quarter=(c-4)&3. All tiles SW64.
__device__ __forceinline__ void load_chunk(
    int c, char* smem, uint32_t stageOff, int m0, int tid,
    const float* __restrict__ X,
    const __nv_bfloat16* __restrict__ Bh, const __nv_bfloat16* __restrict__ Bl, int n)
{
    uint32_t sbase = s2u(smem) + stageOff;
    if (c < 4) {
        // B tiles via cp.async: 2 tiles x 512 units of 16B = 1024 units, 4/thread
#pragma unroll
        for (int i = 0; i < 4; i++) {
            int idx = tid + i * 256;
            int q = idx >> 9, j = idx & 511;
            int row = j >> 2, s16 = j & 3;
            uint32_t byte = row * 64 + s16 * 16;
            uint32_t dstp = sbase + 16384 + q * 8192 + (byte ^ ((byte >> 3) & 0x30));
            const char* srcp = (const char*)(q ? Bl : Bh) + (size_t)row * 1536 + c * 64 + s16 * 16;
            asm volatile("cp.async.cg.shared.global [%0], [%1], 16;" :: "r"(dstp), "l"(srcp));
        }
        asm volatile("cp.async.commit_group;" ::: "memory");
        // A tiles: f32 X -> bf16 hi/lo split -> swizzled STS (16 cols per thread)
        int row = tid >> 1, h = tid & 1;
        int node = m0 + row;
        const float* xr = X + (size_t)node * 128 + c * 32 + h * 16;
#pragma unroll
        for (int j = 0; j < 2; j++) {
            float v[8];
            if (node < n) {
                float4 f0 = __ldg((const float4*)(xr + j * 8));
                float4 f1 = __ldg((const float4*)(xr + j * 8) + 1);
                v[0] = f0.x; v[1] = f0.y; v[2] = f0.z; v[3] = f0.w;
                v[4] = f1.x; v[5] = f1.y; v[6] = f1.z; v[7] = f1.w;
            } else {
#pragma unroll
                for (int q = 0; q < 8; q++) v[q] = 0.f;
            }
            uint4 hi, lo;
            pack8(v, hi, lo);
            uint32_t byte = row * 64 + h * 32 + j * 16;
            uint32_t sw = byte ^ ((byte >> 3) & 0x30);
            *(uint4*)(smem + stageOff + sw) = hi;
            *(uint4*)(smem + stageOff + 8192 + sw) = lo;
        }
    } else {
        int rc = (c - 4) >> 2;                 // relation 0..4
        int qr = (c - 4) & 3;                  // quarter: cols qr*32..qr*32+31
        const unsigned char* agbase =
            g_AG + ((size_t)rc * NN_PAD + m0) * 512 + qr * 64;
        // 4 tiles x 512 units = 2048 units, 8/thread
#pragma unroll
        for (int i = 0; i < 8; i++) {
            int idx = tid + i * 256;
            int sub = idx >> 9, j = idx & 511;
            int row = j >> 2, s16 = j & 3;
            uint32_t byte = row * 64 + s16 * 16;
            uint32_t dstp = sbase + sub * 8192 + (byte ^ ((byte >> 3) & 0x30));
            const char* srcp;
            if (sub == 0)      srcp = (const char*)agbase + (size_t)row * 512 + s16 * 16;
            else if (sub == 1) srcp = (const char*)agbase + (size_t)row * 512 + 256 + s16 * 16;
            else if (sub == 2) srcp = (const char*)Bh + (size_t)row * 1536 + c * 64 + s16 * 16;
            else               srcp = (const char*)Bl + (size_t)row * 1536 + c * 64 + s16 * 16;
            asm volatile("cp.async.cg.shared.global [%0], [%1], 16;" :: "r"(dstp), "l"(srcp));
        }
        asm volatile("cp.async.commit_group;" ::: "memory");
    }
}
#endif  // HAS_TCGEN05

__global__ void __launch_bounds__(256, 2) k_mma(
    const float* __restrict__ X,
    const __nv_bfloat16* __restrict__ Bh, const __nv_bfloat16* __restrict__ Bl,
    const float* __restrict__ bias, float* __restrict__ Y, int n)
{
#if HAS_TCGEN05
    extern __shared__ char smem[];
    uint32_t sb = s2u(smem);
    int tid = threadIdx.x;
    int wid = tid >> 5, lane = tid & 31;
    int m0 = blockIdx.x * 128;

    if (wid == 0) {
        asm volatile(
            "tcgen05.alloc.cta_group::1.sync.aligned.shared::cta.b32 [%0], %1;"
            :: "r"(sb), "r"(128u) : "memory");
        asm volatile("tcgen05.relinquish_alloc_permit.cta_group::1.sync.aligned;");
    }
    if (tid == 0) {
        mbar_init(sb + 16, 1);
        mbar_init(sb + 24, 1);
        mbar_init(sb + 32, 1);
    }
    __syncthreads();
    uint32_t tmem;
    asm volatile("ld.shared.b32 %0, [%1];" : "=r"(tmem) : "r"(sb));

    load_chunk(0, smem, SMEM_TILES + 0 * STAGE_BYTES, m0, tid, X, Bh, Bl, n);
    load_chunk(1, smem, SMEM_TILES + 1 * STAGE_BYTES, m0, tid, X, Bh, Bl, n);

#pragma unroll 4
    for (int c = 0; c < NCHUNK; c++) {
        // 1) chunk c's data ready
        if (c <= NCHUNK - 2) asm volatile("cp.async.wait_group 1;" ::: "memory");
        else                 asm volatile("cp.async.wait_group 0;" ::: "memory");
        __syncthreads();
        // 2) issue MMA c
        if (tid == 0) {
            asm volatile("fence.proxy.async.shared::cta;" ::: "memory");
            uint32_t tb = sb + SMEM_TILES + (c % 3) * STAGE_BYTES;
            uint64_t dAh = sdesc64(tb);
            uint64_t dAl = sdesc64(tb + 8192);
            uint64_t dBh = sdesc64(tb + 16384);
            uint64_t dBl = sdesc64(tb + 24576);
#pragma unroll
            for (int ks = 0; ks < 2; ks++) {
                uint32_t e0 = (c == 0 && ks == 0) ? 0u : 1u;
                mma_f16_ss(tmem, dAh + ks * 2, dBh + ks * 2, MMA_IDESC, e0);
                mma_f16_ss(tmem, dAh + ks * 2, dBl + ks * 2, MMA_IDESC, 1u);
                mma_f16_ss(tmem, dAl + ks * 2, dBh + ks * 2, MMA_IDESC, 1u);
            }
            mma_commit(sb + 16 + (c % 3) * 8);
        }
        // 3) wait MMA c-1 (frees buffer (c+2)%3)
        if (c >= 1) {
            int t = c - 1;
            mbar_wait(sb + 16 + (t % 3) * 8, (t / 3) & 1);
        }
        // 4) loads for chunk c+2
        if (c + 2 < NCHUNK)
            load_chunk(c + 2, smem, SMEM_TILES + ((c + 2) % 3) * STAGE_BYTES,
                       m0, tid, X, Bh, Bl, n);
    }
    // final: chunk 23 commit on mbar (23%3)=2 -> parity ((23/3)&1)=1
    mbar_wait(sb + 32, (((NCHUNK - 1) / 3) & 1));
    asm volatile("tcgen05.fence::after_thread_sync;" ::: "memory");

    // ---- epilogue: TMEM -> bias+relu -> SMEM transpose -> coalesced f32 stores ----
    float* smF = (float*)(smem + SMEM_TILES);   // [128][129] f32 (66KB, fits)
    int sp = wid & 3, hh = wid >> 2;
#pragma unroll
    for (int p = 0; p < 2; p++) {
        uint32_t r[32];
        LDTM_X32(r, tmem + hh * 64 + p * 32);
        asm volatile("tcgen05.wait::ld.sync.aligned;" ::: "memory");
        int cb = hh * 64 + p * 32;
#pragma unroll
        for (int j = 0; j < 32; j++) {
            float v = __uint_as_float(r[j]) + __ldg(&bias[cb + j]);
            smF[(sp * 32 + lane) * 129 + cb + j] = fmaxf(v, 0.f);
        }
    }
    __syncthreads();
    for (int idx = tid; idx < 4096; idx += 256) {
        int row = idx >> 5, q = idx & 31;
        int grow = m0 + row;
        if (grow < n) {
            float* s = &smF[row * 129 + q * 4];
            float4 o;
            o.x = s[0]; o.y = s[1]; o.z = s[2]; o.w = s[3];
            *(float4*)(Y + (size_t)grow * 128 + q * 4) = o;
        }
    }
    __syncthreads();
    if (wid == 0) {
        asm volatile(
            "tcgen05.dealloc.cta_group::1.sync.aligned.b32 %0, %1;"
            :: "r"(tmem), "r"(128u));
    }
#else
    // ---- fallback (family-generic PTX pass; never used when sm_103a SASS loads) ----
    int tid = threadIdx.x;
    int m0 = blockIdx.x * 128;
    for (int o = tid; o < 128 * 128; o += 256) {
        int row = m0 + (o >> 7), col = o & 127;
        if (row >= n) continue;
        float acc = bias[col];
        for (int k = 0; k < 128; k++) {
            float b = __bfloat162float(Bh[(size_t)col * KTOT + k]) +
                      __bfloat162float(Bl[(size_t)col * KTOT + k]);
            acc += X[(size_t)row * 128 + k] * b;
        }
        for (int r = 0; r < NREL; r++) {
            const unsigned char* base = g_AG + ((size_t)r * NN_PAD + row) * 512;
            const __nv_bfloat16* ph = (const __nv_bfloat16*)base;
            const __nv_bfloat16* pl = (const __nv_bfloat16*)(base + 256);
            for (int k = 0; k < 128; k++) {
                float a = __bfloat162float(ph[k]) + __bfloat162float(pl[k]);
                float b = __bfloat162float(Bh[(size_t)col * KTOT + 128 + r * 128 + k]) +
                          __bfloat162float(Bl[(size_t)col * KTOT + 128 + r * 128 + k]);
                acc += a * b;
            }
        }
        Y[(size_t)row * 128 + col] = fmaxf(acc, 0.f);
    }
#endif
}

// ---------------- launch ----------------
extern "C" void kernel_launch(void* const* d_in, const int* in_sizes, int n_in,
                              void* d_out, int out_size) {
    const float* x  = (const float*)d_in[0];
    const int*   ei = (const int*)d_in[1];
    const int*   et = (const int*)d_in[2];
    const float* W1 = (const float*)d_in[3];
    const float* r1 = (const float*)d_in[4];
    const float* b1 = (const float*)d_in[5];
    const float* W2 = (const float*)d_in[6];
    const float* r2 = (const float*)d_in[7];
    const float* b2 = (const float*)d_in[8];
    const float* W3 = (const float*)d_in[9];
    const float* r3 = (const float*)d_in[10];
    const float* b3 = (const float*)d_in[11];
    float* out = (float*)d_out;

    int n = in_sizes[0] / F;
    int E = in_sizes[1] / 2;
    const int* src = ei;
    const int* dst = ei + E;
    int m = n * NREL;

    float *pB1, *pB2;
    __nv_bfloat16 *pBh, *pBl;
    cudaGetSymbolAddress((void**)&pB1, g_B1);
    cudaGetSymbolAddress((void**)&pB2, g_B2);
    cudaGetSymbolAddress((void**)&pBh, g_Bh);
    cudaGetSymbolAddress((void**)&pBl, g_Bl);

    static int smem_set = 0;
    if (!smem_set) {
        cudaFuncSetAttribute(k_mma, cudaFuncAttributeMaxDynamicSharedMemorySize, SMEM_TOTAL);
        smem_set = 1;
    }

    int gb = (m * 32 + 255) / 256;       // one warp per (node, rel) bucket
    int mb = (n + 127) / 128;

    k_csr<<<CSR_NB, 1024>>>(src, dst, et, E, m);
    k_prepB<<<(3 * BLAYER + 255) / 256, 256>>>(W1, r1, W2, r2, W3, r3);
    // layer 1  (k_mma is 4th launch -> ncu capture target)
    k_gather<<<gb, 256>>>(x, n);
    k_mma<<<mb, 256, SMEM_TOTAL>>>(x, pBh, pBl, b1, pB1, n);
    // layer 2
    k_gather<<<gb, 256>>>(pB1, n);
    k_mma<<<mb, 256, SMEM_TOTAL>>>(pB1, pBh + BLAYER, pBl + BLAYER, b2, pB2, n);
    // layer 3
    k_gather<<<gb, 256>>>(pB2, n);
    k_mma<<<mb, 256, SMEM_TOTAL>>>(pB2, pBh + 2 * BLAYER, pBl + 2 * BLAYER, b3, out, n);
}

// round 12
// speedup vs baseline: 1.0073x; 1.0073x over previous
#include <cuda_runtime.h>
#include <cuda_bf16.h>
#include <cstdint>

#define NN      100000
#define NE      1600000
#define F       128
#define NREL    5
#define NN_PAD  100096          // 782 * 128
#define KTOT    768
#define BLAYER  98304           // 128 * 768 per-layer B elements
#define M5      (NN * NREL)
#define CSR_NB  120             // resident blocks for software grid sync
#define NQ      4               // node-quarters per layer (L2-resident AG)
#define QTILES  196             // tiles per quarter (last: 782-3*196=194)

#if defined(__CUDA_ARCH_FEAT_SM103_ALL) || defined(__CUDA_ARCH_FEAT_SM100_ALL)
#define HAS_TCGEN05 1
#else
#define HAS_TCGEN05 0
#endif

// ---------------- device scratch (no allocations allowed) ----------------
// AG layout: [rel][node][512B block] = 128 bf16 hi (256B) then 128 bf16 lo (256B)
__device__ __align__(256) unsigned char g_AG[(size_t)NREL * NN_PAD * 512];
__device__ __align__(256) __nv_bfloat16 g_Bh[3 * BLAYER];   // weights hi [l][n][k]
__device__ __align__(256) __nv_bfloat16 g_Bl[3 * BLAYER];
__device__ float g_B1[(size_t)NN * F];
__device__ float g_B2[(size_t)NN * F];
__device__ int   g_deg5[M5];
__device__ int   g_off5[M5 + 1];
__device__ int   g_cur5[M5];
__device__ int   g_edges[NE];                 // src, sorted by (dst, rel)
__device__ int   g_bsums[512];
__device__ int   g_bar = 0;
__device__ volatile unsigned g_sense = 0;

// ---------------- small helpers ----------------
__device__ __forceinline__ uint32_t s2u(const void* p) {
    return (uint32_t)__cvta_generic_to_shared(p);
}
__device__ __forceinline__ void bsplit(float v, __nv_bfloat16& h, __nv_bfloat16& l) {
    h = __float2bfloat16_rn(v);
    l = __float2bfloat16_rn(v - __bfloat162float(h));
}
__device__ __forceinline__ void pack8(const float* f, uint4& hi, uint4& lo) {
    uint32_t h[4], l[4];
#pragma unroll
    for (int i = 0; i < 4; i++) {
        __nv_bfloat16 h0, l0, h1, l1;
        bsplit(f[2 * i], h0, l0);
        bsplit(f[2 * i + 1], h1, l1);
        __nv_bfloat162 hh = __halves2bfloat162(h0, h1);
        __nv_bfloat162 ll = __halves2bfloat162(l0, l1);
        h[i] = *(uint32_t*)&hh;
        l[i] = *(uint32_t*)&ll;
    }
    hi = make_uint4(h[0], h[1], h[2], h[3]);
    lo = make_uint4(l[0], l[1], l[2], l[3]);
}
__device__ __forceinline__ void mbar_init(uint32_t a, uint32_t cnt) {
    asm volatile("mbarrier.init.shared.b64 [%0], %1;" :: "r"(a), "r"(cnt) : "memory");
}
__device__ __forceinline__ void mbar_wait(uint32_t a, int par) {
    asm volatile(
        "{\n\t.reg .pred P;\n"
        "WL%=:\n\t"
        "mbarrier.try_wait.parity.acquire.cta.shared::cta.b64 P, [%0], %1, 0x989680;\n\t"
        "@P bra WD%=;\n\t"
        "bra WL%=;\n"
        "WD%=:\n\t}"
        :: "r"(a), "r"(par) : "memory");
}
__device__ __forceinline__ void gsync(int nb) {
    __syncthreads();
    if (threadIdx.x == 0) {
        unsigned s = g_sense;
        __threadfence();
        if (atomicAdd(&g_bar, 1) == nb - 1) {
            g_bar = 0;
            __threadfence();
            g_sense = s + 1;
        } else {
            while (g_sense == s) { }
        }
        __threadfence();
    }
    __syncthreads();
}

// ---------------- single-kernel CSR build: zero -> hist -> scan -> place ----------------
__global__ void __launch_bounds__(1024, 1) k_csr(
    const int* __restrict__ src, const int* __restrict__ dst,
    const int* __restrict__ et, int E, int m)
{
    const int NB = gridDim.x;
    int tid = threadIdx.x, bid = blockIdx.x;
    int gt = bid * 1024 + tid, gs = NB * 1024;
    __shared__ int sh[1024];

    for (int i = gt; i < m; i += gs) g_deg5[i] = 0;
    // zero AG rows for padded nodes (n..NN_PAD) so last-tile MMA reads zeros
    for (int r = 0; r < NREL; r++) {
        unsigned char* p = g_AG + ((size_t)r * NN_PAD + NN) * 512;
        size_t bytes = (size_t)(NN_PAD - NN) * 512;
        for (size_t i = (size_t)gt * 16; i + 16 <= bytes; i += (size_t)gs * 16)
            *(uint4*)(p + i) = make_uint4(0, 0, 0, 0);
    }
    gsync(NB);

    for (int e = gt; e < E; e += gs) atomicAdd(&g_deg5[dst[e] * NREL + et[e]], 1);
    gsync(NB);

    int RB = (m + NB - 1) / NB;
    int CH = (RB + 1023) / 1024;
    int base = bid * RB;
    int lim = min(base + RB, m);
    int i0 = base + tid * CH;
    int mysum = 0;
#pragma unroll 4
    for (int j = 0; j < CH; j++) {
        int i = i0 + j;
        if (i < lim) mysum += g_deg5[i];
    }
    sh[tid] = mysum;
    __syncthreads();
    for (int d = 1; d < 1024; d <<= 1) {
        int t = (tid >= d) ? sh[tid - d] : 0;
        __syncthreads();
        sh[tid] += t;
        __syncthreads();
    }
    if (tid == 1023) g_bsums[bid] = sh[1023];
    int myoff_local = sh[tid] - mysum;
    gsync(NB);

    if (bid == 0) {
        int v = (tid < NB) ? g_bsums[tid] : 0;
        sh[tid] = v;
        __syncthreads();
        for (int d = 1; d < 1024; d <<= 1) {
            int t = (tid >= d) ? sh[tid - d] : 0;
            __syncthreads();
            sh[tid] += t;
            __syncthreads();
        }
        if (tid < NB) g_bsums[tid] = sh[tid] - v;
    }
    gsync(NB);

    int run = g_bsums[bid] + myoff_local;
#pragma unroll 4
    for (int j = 0; j < CH; j++) {
        int i = i0 + j;
        if (i < lim) {
            g_off5[i] = run;
            g_cur5[i] = run;
            run += g_deg5[i];
        }
    }
    if (gt == 0) g_off5[m] = E;
    gsync(NB);

    for (int e = gt; e < E; e += gs) {
        int b = dst[e] * NREL + et[e];
        int pos = atomicAdd(&g_cur5[b], 1);
        g_edges[pos] = src[e];
    }
}

// ---------------- weights -> transposed bf16 hi/lo B matrices ----------------
__global__ void k_prepB(const float* __restrict__ W1, const float* __restrict__ r1,
                        const float* __restrict__ W2, const float* __restrict__ r2,
                        const float* __restrict__ W3, const float* __restrict__ r3) {
    int idx = blockIdx.x * blockDim.x + threadIdx.x;
    if (idx >= 3 * BLAYER) return;
    int l = idx / BLAYER;
    int rem = idx % BLAYER;
    int nn = rem / KTOT;
    int k = rem % KTOT;
    const float* Wl = (l == 0) ? W1 : ((l == 1) ? W2 : W3);
    const float* rl = (l == 0) ? r1 : ((l == 1) ? r2 : r3);
    float v = (k < 128) ? rl[k * 128 + nn] : Wl[(size_t)(k - 128) * 128 + nn];
    __nv_bfloat16 h, lo;
    bsplit(v, h, lo);
    g_Bh[idx] = h;
    g_Bl[idx] = lo;
}

// ---------------- gather: one warp per (node, rel) bucket, node range [n0, n1) ----------------
__global__ void k_gather(const float* __restrict__ X, int n0, int n1) {
    int b = (blockIdx.x * blockDim.x + threadIdx.x) >> 5;
    if (b >= (n1 - n0) * NREL) return;
    int lane = threadIdx.x & 31;
    int node = n0 + b / NREL, rel = b % NREL;
    int bk = node * NREL + rel;
    int beg = g_off5[bk], end = g_off5[bk + 1];

    float ax = 0.f, ay = 0.f, az = 0.f, aw = 0.f;
    int e = beg;
    for (; e + 4 <= end; e += 4) {
        int s0 = __ldg(&g_edges[e]);
        int s1 = __ldg(&g_edges[e + 1]);
        int s2 = __ldg(&g_edges[e + 2]);
        int s3 = __ldg(&g_edges[e + 3]);
        float4 v0 = __ldg((const float4*)X + (size_t)s0 * 32 + lane);
        float4 v1 = __ldg((const float4*)X + (size_t)s1 * 32 + lane);
        float4 v2 = __ldg((const float4*)X + (size_t)s2 * 32 + lane);
        float4 v3 = __ldg((const float4*)X + (size_t)s3 * 32 + lane);
        ax += (v0.x + v1.x) + (v2.x + v3.x);
        ay += (v0.y + v1.y) + (v2.y + v3.y);
        az += (v0.z + v1.z) + (v2.z + v3.z);
        aw += (v0.w + v1.w) + (v2.w + v3.w);
    }
    for (; e < end; e++) {
        int s0 = __ldg(&g_edges[e]);
        float4 v0 = __ldg((const float4*)X + (size_t)s0 * 32 + lane);
        ax += v0.x; ay += v0.y; az += v0.z; aw += v0.w;
    }
    int cnt = end - beg;
    float sc = cnt ? 1.f / (float)cnt : 0.f;
    float f0 = ax * sc, f1 = ay * sc, f2 = az * sc, f3 = aw * sc;

    __nv_bfloat16 h0, l0, h1, l1, h2, l2, h3, l3;
    bsplit(f0, h0, l0); bsplit(f1, h1, l1);
    bsplit(f2, h2, l2); bsplit(f3, h3, l3);
    __nv_bfloat162 hA = __halves2bfloat162(h0, h1);
    __nv_bfloat162 hB = __halves2bfloat162(h2, h3);
    __nv_bfloat162 lA = __halves2bfloat162(l0, l1);
    __nv_bfloat162 lB = __halves2bfloat162(l2, l3);
    // contiguous 512B block per bucket: hi[256B] | lo[256B]
    unsigned char* base = g_AG + ((size_t)rel * NN_PAD + node) * 512;
    *(uint2*)(base + lane * 8)       = make_uint2(*(uint32_t*)&hA, *(uint32_t*)&hB);
    *(uint2*)(base + 256 + lane * 8) = make_uint2(*(uint32_t*)&lA, *(uint32_t*)&lB);
}

// ---------------- tcgen05 fused GEMM ----------------
// Y = relu([X | A0..A4] @ Bt + bias), 3-term bf16 split.
// 24 K-chunks of 32; SW64 tiles (128 rows x 64B); 3 stages of 32KB -> 2 CTAs/SM.
#define SMEM_TILES  1024
#define STAGE_BYTES 32768       // Ah(8K) Al(8K) Bh(8K) Bl(8K)
#define SMEM_TOTAL  (SMEM_TILES + 3 * STAGE_BYTES)
#define NCHUNK      24
#define MMA_IDESC   ((1u << 4) | (1u << 7) | (1u << 10) | (16u << 17) | (8u << 24))

#if HAS_TCGEN05
__device__ __forceinline__ uint64_t sdesc64(uint32_t a) {
    // SW64 (layout=4), version=1 (Blackwell), SBO=32, LBO=1 (K-major, 64B rows)
    return ((uint64_t)4 << 61) | ((uint64_t)1 << 46) | ((uint64_t)32 << 32) |
           ((uint64_t)1 << 16) | (uint64_t)((a >> 4) & 0x3FFF);
}
__device__ __forceinline__ void mma_f16_ss(uint32_t d, uint64_t ad, uint64_t bd,
                                           uint32_t idesc, uint32_t en) {
    asm volatile(
        "{\n\t.reg .pred p;\n\t"
        "setp.ne.u32 p, %4, 0;\n\t"
        "tcgen05.mma.cta_group::1.kind::f16 [%0], %1, %2, %3, {%5, %5, %5, %5}, p;\n\t}"
        :: "r"(d), "l"(ad), "l"(bd), "r"(idesc), "r"(en), "r"(0u) : "memory");
}
__device__ __forceinline__ void mma_commit(uint32_t mbar) {
    asm volatile(
        "tcgen05.commit.cta_group::1.mbarrier::arrive::one.shared::cluster.b64 [%0];"
        :: "r"(mbar) : "memory");
}
#define LDTM_X32(r, addr)                                                        \
    asm volatile(                                                                \
        "tcgen05.ld.sync.aligned.32x32b.x32.b32 "                                \
        "{%0, %1, %2, %3, %4, %5, %6, %7, "                                      \
        " %8, %9, %10, %11, %12, %13, %14, %15, "                                \
        " %16, %17, %18, %19, %20, %21, %22, %23, "                              \
        " %24, %25, %26, %27, %28, %29, %30, %31}, [%32];"                       \
        : "=r"((r)[0]),  "=r"((r)[1]),  "=r"((r)[2]),  "=r"((r)[3]),             \
          "=r"((r)[4]),  "=r"((r)[5]),  "=r"((r)[6]),  "=r"((r)[7]),             \
          "=r"((r)[8]),  "=r"((r)[9]),  "=r"((r)[10]), "=r"((r)[11]),            \
          "=r"((r)[12]), "=r"((r)[13]), "=r"((r)[14]), "=r"((r)[15]),            \
          "=r"((r)[16]), "=r"((r)[17]), "=r"((r)[18]), "=r"((r)[19]),            \
          "=r"((r)[20]), "=r"((r)[21]), "=r"((r)[22]), "=r"((r)[23]),            \
          "=r"((r)[24]), "=r"((r)[25]), "=r"((r)[26]), "=r"((r)[27]),            \
          "=r"((r)[28]), "=r"((r)[29]), "=r"((r)[30]), "=r"((r)[31])             \
        : "r"(addr))

// chunks 0..3: A from f32 X (LDG+split+STS), B via cp.async.
// chunks 4..23: A from AG: rel=(c-4)>>2, quarter=(c-4)&3. All tiles SW64.
__device__ __forceinline__ void load_chunk(
    int c, char* smem, uint32_t stageOff, int m0, int tid,
    const float* __restrict__ X,
    const __nv_bfloat16* __restrict__ Bh, const __nv_bfloat16* __restrict__ Bl, int n)
{
    uint32_t sbase = s2u(smem) + stageOff;
    if (c < 4) {
        // B tiles via cp.async: 2 tiles x 512 units of 16B = 1024 units, 4/thread
#pragma unroll
        for (int i = 0; i < 4; i++) {
            int idx = tid + i * 256;
            int q = idx >> 9, j = idx & 511;
            int row = j >> 2, s16 = j & 3;
            uint32_t byte = row * 64 + s16 * 16;
            uint32_t dstp = sbase + 16384 + q * 8192 + (byte ^ ((byte >> 3) & 0x30));
            const char* srcp = (const char*)(q ? Bl : Bh) + (size_t)row * 1536 + c * 64 + s16 * 16;
            asm volatile("cp.async.cg.shared.global [%0], [%1], 16;" :: "r"(dstp), "l"(srcp));
        }
        asm volatile("cp.async.commit_group;" ::: "memory");
        // A tiles: f32 X -> bf16 hi/lo split -> swizzled STS (16 cols per thread)
        int row = tid >> 1, h = tid & 1;
        int node = m0 + row;
        const float* xr = X + (size_t)node * 128 + c * 32 + h * 16;
#pragma unroll
        for (int j = 0; j < 2; j++) {
            float v[8];
            if (node < n) {
                float4 f0 = __ldg((const float4*)(xr + j * 8));
                float4 f1 = __ldg((const float4*)(xr + j * 8) + 1);
                v[0] = f0.x; v[1] = f0.y; v[2] = f0.z; v[3] = f0.w;
                v[4] = f1.x; v[5] = f1.y; v[6] = f1.z; v[7] = f1.w;
            } else {
#pragma unroll
                for (int q = 0; q < 8; q++) v[q] = 0.f;
            }
            uint4 hi, lo;
            pack8(v, hi, lo);
            uint32_t byte = row * 64 + h * 32 + j * 16;
            uint32_t sw = byte ^ ((byte >> 3) & 0x30);
            *(uint4*)(smem + stageOff + sw) = hi;
            *(uint4*)(smem + stageOff + 8192 + sw) = lo;
        }
    } else {
        int rc = (c - 4) >> 2;                 // relation 0..4
        int qr = (c - 4) & 3;                  // quarter: cols qr*32..qr*32+31
        const unsigned char* agbase =
            g_AG + ((size_t)rc * NN_PAD + m0) * 512 + qr * 64;
        // 4 tiles x 512 units = 2048 units, 8/thread
#pragma unroll
        for (int i = 0; i < 8; i++) {
            int idx = tid + i * 256;
            int sub = idx >> 9, j = idx & 511;
            int row = j >> 2, s16 = j & 3;
            uint32_t byte = row * 64 + s16 * 16;
            uint32_t dstp = sbase + sub * 8192 + (byte ^ ((byte >> 3) & 0x30));
            const char* srcp;
            if (sub == 0)      srcp = (const char*)agbase + (size_t)row * 512 + s16 * 16;
            else if (sub == 1) srcp = (const char*)agbase + (size_t)row * 512 + 256 + s16 * 16;
            else if (sub == 2) srcp = (const char*)Bh + (size_t)row * 1536 + c * 64 + s16 * 16;
            else               srcp = (const char*)Bl + (size_t)row * 1536 + c * 64 + s16 * 16;
            asm volatile("cp.async.cg.shared.global [%0], [%1], 16;" :: "r"(dstp), "l"(srcp));
        }
        asm volatile("cp.async.commit_group;" ::: "memory");
    }
}
#endif  // HAS_TCGEN05

__global__ void __launch_bounds__(256, 2) k_mma(
    const float* __restrict__ X,
    const __nv_bfloat16* __restrict__ Bh, const __nv_bfloat16* __restrict__ Bl,
    const float* __restrict__ bias, float* __restrict__ Y, int n, int tile0)
{
#if HAS_TCGEN05
    extern __shared__ char smem[];
    uint32_t sb = s2u(smem);
    int tid = threadIdx.x;
    int wid = tid >> 5, lane = tid & 31;
    int m0 = (tile0 + blockIdx.x) * 128;

    if (wid == 0) {
        asm volatile(
            "tcgen05.alloc.cta_group::1.sync.aligned.shared::cta.b32 [%0], %1;"
            :: "r"(sb), "r"(128u) : "memory");
        asm volatile("tcgen05.relinquish_alloc_permit.cta_group::1.sync.aligned;");
    }
    if (tid == 0) {
        mbar_init(sb + 16, 1);
        mbar_init(sb + 24, 1);
        mbar_init(sb + 32, 1);
    }
    __syncthreads();
    uint32_t tmem;
    asm volatile("ld.shared.b32 %0, [%1];" : "=r"(tmem) : "r"(sb));

    load_chunk(0, smem, SMEM_TILES + 0 * STAGE_BYTES, m0, tid, X, Bh, Bl, n);
    load_chunk(1, smem, SMEM_TILES + 1 * STAGE_BYTES, m0, tid, X, Bh, Bl, n);

#pragma unroll 4
    for (int c = 0; c < NCHUNK; c++) {
        // 1) chunk c's data ready
        if (c <= NCHUNK - 2) asm volatile("cp.async.wait_group 1;" ::: "memory");
        else                 asm volatile("cp.async.wait_group 0;" ::: "memory");
        __syncthreads();
        // 2) issue MMA c
        if (tid == 0) {
            asm volatile("fence.proxy.async.shared::cta;" ::: "memory");
            uint32_t tb = sb + SMEM_TILES + (c % 3) * STAGE_BYTES;
            uint64_t dAh = sdesc64(tb);
            uint64_t dAl = sdesc64(tb + 8192);
            uint64_t dBh = sdesc64(tb + 16384);
            uint64_t dBl = sdesc64(tb + 24576);
#pragma unroll
            for (int ks = 0; ks < 2; ks++) {
                uint32_t e0 = (c == 0 && ks == 0) ? 0u : 1u;
                mma_f16_ss(tmem, dAh + ks * 2, dBh + ks * 2, MMA_IDESC, e0);
                mma_f16_ss(tmem, dAh + ks * 2, dBl + ks * 2, MMA_IDESC, 1u);
                mma_f16_ss(tmem, dAl + ks * 2, dBh + ks * 2, MMA_IDESC, 1u);
            }
            mma_commit(sb + 16 + (c % 3) * 8);
        }
        // 3) wait MMA c-1 (frees buffer (c+2)%3)
        if (c >= 1) {
            int t = c - 1;
            mbar_wait(sb + 16 + (t % 3) * 8, (t / 3) & 1);
        }
        // 4) loads for chunk c+2
        if (c + 2 < NCHUNK)
            load_chunk(c + 2, smem, SMEM_TILES + ((c + 2) % 3) * STAGE_BYTES,
                       m0, tid, X, Bh, Bl, n);
    }
    // final: chunk 23 commit on mbar (23%3)=2 -> parity ((23/3)&1)=1
    mbar_wait(sb + 32, (((NCHUNK - 1) / 3) & 1));
    asm volatile("tcgen05.fence::after_thread_sync;" ::: "memory");

    // ---- epilogue: TMEM -> bias+relu -> SMEM transpose -> coalesced f32 stores ----
    float* smF = (float*)(smem + SMEM_TILES);   // [128][129] f32 (66KB, fits)
    int sp = wid & 3, hh = wid >> 2;
#pragma unroll
    for (int p = 0; p < 2; p++) {
        uint32_t r[32];
        LDTM_X32(r, tmem + hh * 64 + p * 32);
        asm volatile("tcgen05.wait::ld.sync.aligned;" ::: "memory");
        int cb = hh * 64 + p * 32;
#pragma unroll
        for (int j = 0; j < 32; j++) {
            float v = __uint_as_float(r[j]) + __ldg(&bias[cb + j]);
            smF[(sp * 32 + lane) * 129 + cb + j] = fmaxf(v, 0.f);
        }
    }
    __syncthreads();
    for (int idx = tid; idx < 4096; idx += 256) {
        int row = idx >> 5, q = idx & 31;
        int grow = m0 + row;
        if (grow < n) {
            float* s = &smF[row * 129 + q * 4];
            float4 o;
            o.x = s[0]; o.y = s[1]; o.z = s[2]; o.w = s[3];
            *(float4*)(Y + (size_t)grow * 128 + q * 4) = o;
        }
    }
    __syncthreads();
    if (wid == 0) {
        asm volatile(
            "tcgen05.dealloc.cta_group::1.sync.aligned.b32 %0, %1;"
            :: "r"(tmem), "r"(128u));
    }
#else
    // ---- fallback (family-generic PTX pass; never used when sm_103a SASS loads) ----
    int tid = threadIdx.x;
    int m0 = (tile0 + blockIdx.x) * 128;
    for (int o = tid; o < 128 * 128; o += 256) {
        int row = m0 + (o >> 7), col = o & 127;
        if (row >= n) continue;
        float acc = bias[col];
        for (int k = 0; k < 128; k++) {
            float b = __bfloat162float(Bh[(size_t)col * KTOT + k]) +
                      __bfloat162float(Bl[(size_t)col * KTOT + k]);
            acc += X[(size_t)row * 128 + k] * b;
        }
        for (int r = 0; r < NREL; r++) {
            const unsigned char* base = g_AG + ((size_t)r * NN_PAD + row) * 512;
            const __nv_bfloat16* ph = (const __nv_bfloat16*)base;
            const __nv_bfloat16* pl = (const __nv_bfloat16*)(base + 256);
            for (int k = 0; k < 128; k++) {
                float a = __bfloat162float(ph[k]) + __bfloat162float(pl[k]);
                float b = __bfloat162float(Bh[(size_t)col * KTOT + 128 + r * 128 + k]) +
                          __bfloat162float(Bl[(size_t)col * KTOT + 128 + r * 128 + k]);
                acc += a * b;
            }
        }
        Y[(size_t)row * 128 + col] = fmaxf(acc, 0.f);
    }
#endif
}

// ---------------- launch ----------------
extern "C" void kernel_launch(void* const* d_in, const int* in_sizes, int n_in,
                              void* d_out, int out_size) {
    const float* x  = (const float*)d_in[0];
    const int*   ei = (const int*)d_in[1];
    const int*   et = (const int*)d_in[2];
    const float* W1 = (const float*)d_in[3];
    const float* r1 = (const float*)d_in[4];
    const float* b1 = (const float*)d_in[5];
    const float* W2 = (const float*)d_in[6];
    const float* r2 = (const float*)d_in[7];
    const float* b2 = (const float*)d_in[8];
    const float* W3 = (const float*)d_in[9];
    const float* r3 = (const float*)d_in[10];
    const float* b3 = (const float*)d_in[11];
    float* out = (float*)d_out;

    int n = in_sizes[0] / F;
    int E = in_sizes[1] / 2;
    const int* src = ei;
    const int* dst = ei + E;
    int m = n * NREL;

    float *pB1, *pB2;
    __nv_bfloat16 *pBh, *pBl;
    cudaGetSymbolAddress((void**)&pB1, g_B1);
    cudaGetSymbolAddress((void**)&pB2, g_B2);
    cudaGetSymbolAddress((void**)&pBh, g_Bh);
    cudaGetSymbolAddress((void**)&pBl, g_Bl);

    static int smem_set = 0;
    if (!smem_set) {
        cudaFuncSetAttribute(k_mma, cudaFuncAttributeMaxDynamicSharedMemorySize, SMEM_TOTAL);
        smem_set = 1;
    }

    int totTiles = (n + 127) / 128;

    k_csr<<<CSR_NB, 1024>>>(src, dst, et, E, m);
    k_prepB<<<(3 * BLAYER + 255) / 256, 256>>>(W1, r1, W2, r2, W3, r3);

    const float* Xl[3] = {x, pB1, pB2};
    float* Yl[3] = {pB1, pB2, out};
    const float* Bs[3] = {b1, b2, b3};

    for (int l = 0; l < 3; l++) {
        for (int q = 0; q < NQ; q++) {
            int t0 = q * QTILES;
            if (t0 >= totTiles) break;
            int t1 = min(totTiles, t0 + QTILES);
            int n0 = t0 * 128;
            int n1 = min(n, t1 * 128);
            int gb = ((n1 - n0) * NREL * 32 + 255) / 256;
            // gather quarter q, then MMA it while its AG is L2-resident
            k_gather<<<gb, 256>>>(Xl[l], n0, n1);
            k_mma<<<t1 - t0, 256, SMEM_TOTAL>>>(Xl[l], pBh + l * BLAYER, pBl + l * BLAYER,
                                                Bs[l], Yl[l], n, t0);
        }
    }
}

// round 13
// speedup vs baseline: 1.0598x; 1.0521x over previous
#include <cuda_runtime.h>
#include <cuda_bf16.h>
#include <cstdint>

#define NN      100000
#define NE      1600000
#define F       128
#define NREL    5
#define NN_PAD  100096          // 782 * 128
#define KTOT    768
#define BLAYER  98304           // 128 * 768 per-layer B elements
#define M5      (NN * NREL)
#define CSR_NB  120             // resident blocks for software grid sync

#if defined(__CUDA_ARCH_FEAT_SM103_ALL) || defined(__CUDA_ARCH_FEAT_SM100_ALL)
#define HAS_TCGEN05 1
#else
#define HAS_TCGEN05 0
#endif

// ---------------- device scratch (no allocations allowed) ----------------
// AG layout: [rel][node][512B block] = 128 bf16 hi (256B) then 128 bf16 lo (256B)
__device__ __align__(256) unsigned char g_AG[(size_t)NREL * NN_PAD * 512];
__device__ __align__(256) __nv_bfloat16 g_Bh[3 * BLAYER];   // weights hi [l][n][k]
__device__ __align__(256) __nv_bfloat16 g_Bl[3 * BLAYER];
__device__ float g_B1[(size_t)NN * F];
__device__ float g_B2[(size_t)NN * F];
__device__ int   g_deg5[M5];
__device__ int   g_off5[M5 + 1];
__device__ int   g_cur5[M5];
__device__ int   g_edges[NE];                 // src, sorted by (dst, rel)
__device__ int   g_bsums[512];
__device__ int   g_bar = 0;
__device__ volatile unsigned g_sense = 0;

// ---------------- small helpers ----------------
__device__ __forceinline__ uint32_t s2u(const void* p) {
    return (uint32_t)__cvta_generic_to_shared(p);
}
__device__ __forceinline__ void bsplit(float v, __nv_bfloat16& h, __nv_bfloat16& l) {
    h = __float2bfloat16_rn(v);
    l = __float2bfloat16_rn(v - __bfloat162float(h));
}
__device__ __forceinline__ void pack8(const float* f, uint4& hi, uint4& lo) {
    uint32_t h[4], l[4];
#pragma unroll
    for (int i = 0; i < 4; i++) {
        __nv_bfloat16 h0, l0, h1, l1;
        bsplit(f[2 * i], h0, l0);
        bsplit(f[2 * i + 1], h1, l1);
        __nv_bfloat162 hh = __halves2bfloat162(h0, h1);
        __nv_bfloat162 ll = __halves2bfloat162(l0, l1);
        h[i] = *(uint32_t*)&hh;
        l[i] = *(uint32_t*)&ll;
    }
    hi = make_uint4(h[0], h[1], h[2], h[3]);
    lo = make_uint4(l[0], l[1], l[2], l[3]);
}
__device__ __forceinline__ void mbar_init(uint32_t a, uint32_t cnt) {
    asm volatile("mbarrier.init.shared.b64 [%0], %1;" :: "r"(a), "r"(cnt) : "memory");
}
__device__ __forceinline__ void mbar_wait(uint32_t a, int par) {
    asm volatile(
        "{\n\t.reg .pred P;\n"
        "WL%=:\n\t"
        "mbarrier.try_wait.parity.acquire.cta.shared::cta.b64 P, [%0], %1, 0x989680;\n\t"
        "@P bra WD%=;\n\t"
        "bra WL%=;\n"
        "WD%=:\n\t}"
        :: "r"(a), "r"(par) : "memory");
}
__device__ __forceinline__ void gsync(int nb) {
    __syncthreads();
    if (threadIdx.x == 0) {
        unsigned s = g_sense;
        __threadfence();
        if (atomicAdd(&g_bar, 1) == nb - 1) {
            g_bar = 0;
            __threadfence();
            g_sense = s + 1;
        } else {
            while (g_sense == s) { }
        }
        __threadfence();
    }
    __syncthreads();
}

// ---------------- single-kernel CSR build: zero -> hist -> scan -> place ----------------
__global__ void __launch_bounds__(1024, 1) k_csr(
    const int* __restrict__ src, const int* __restrict__ dst,
    const int* __restrict__ et, int E, int m)
{
    const int NB = gridDim.x;
    int tid = threadIdx.x, bid = blockIdx.x;
    int gt = bid * 1024 + tid, gs = NB * 1024;
    __shared__ int sh[1024];

    for (int i = gt; i < m; i += gs) g_deg5[i] = 0;
    // zero AG rows for padded nodes (n..NN_PAD) so last-tile MMA reads zeros
    for (int r = 0; r < NREL; r++) {
        unsigned char* p = g_AG + ((size_t)r * NN_PAD + NN) * 512;
        size_t bytes = (size_t)(NN_PAD - NN) * 512;
        for (size_t i = (size_t)gt * 16; i + 16 <= bytes; i += (size_t)gs * 16)
            *(uint4*)(p + i) = make_uint4(0, 0, 0, 0);
    }
    gsync(NB);

    for (int e = gt; e < E; e += gs) atomicAdd(&g_deg5[dst[e] * NREL + et[e]], 1);
    gsync(NB);

    int RB = (m + NB - 1) / NB;
    int CH = (RB + 1023) / 1024;
    int base = bid * RB;
    int lim = min(base + RB, m);
    int i0 = base + tid * CH;
    int mysum = 0;
#pragma unroll 4
    for (int j = 0; j < CH; j++) {
        int i = i0 + j;
        if (i < lim) mysum += g_deg5[i];
    }
    sh[tid] = mysum;
    __syncthreads();
    for (int d = 1; d < 1024; d <<= 1) {
        int t = (tid >= d) ? sh[tid - d] : 0;
        __syncthreads();
        sh[tid] += t;
        __syncthreads();
    }
    if (tid == 1023) g_bsums[bid] = sh[1023];
    int myoff_local = sh[tid] - mysum;
    gsync(NB);

    if (bid == 0) {
        int v = (tid < NB) ? g_bsums[tid] : 0;
        sh[tid] = v;
        __syncthreads();
        for (int d = 1; d < 1024; d <<= 1) {
            int t = (tid >= d) ? sh[tid - d] : 0;
            __syncthreads();
            sh[tid] += t;
            __syncthreads();
        }
        if (tid < NB) g_bsums[tid] = sh[tid] - v;
    }
    gsync(NB);

    int run = g_bsums[bid] + myoff_local;
#pragma unroll 4
    for (int j = 0; j < CH; j++) {
        int i = i0 + j;
        if (i < lim) {
            g_off5[i] = run;
            g_cur5[i] = run;
            run += g_deg5[i];
        }
    }
    if (gt == 0) g_off5[m] = E;
    gsync(NB);

    for (int e = gt; e < E; e += gs) {
        int b = dst[e] * NREL + et[e];
        int pos = atomicAdd(&g_cur5[b], 1);
        g_edges[pos] = src[e];
    }
}

// ---------------- weights -> transposed bf16 hi/lo B matrices ----------------
__global__ void k_prepB(const float* __restrict__ W1, const float* __restrict__ r1,
                        const float* __restrict__ W2, const float* __restrict__ r2,
                        const float* __restrict__ W3, const float* __restrict__ r3) {
    int idx = blockIdx.x * blockDim.x + threadIdx.x;
    if (idx >= 3 * BLAYER) return;
    int l = idx / BLAYER;
    int rem = idx % BLAYER;
    int nn = rem / KTOT;
    int k = rem % KTOT;
    const float* Wl = (l == 0) ? W1 : ((l == 1) ? W2 : W3);
    const float* rl = (l == 0) ? r1 : ((l == 1) ? r2 : r3);
    float v = (k < 128) ? rl[k * 128 + nn] : Wl[(size_t)(k - 128) * 128 + nn];
    __nv_bfloat16 h, lo;
    bsplit(v, h, lo);
    g_Bh[idx] = h;
    g_Bl[idx] = lo;
}

// ---------------- gather: one warp per (node, rel) bucket ----------------
// Main loop 4-wide; remainder (<=3 edges) fully predicated so its loads issue
// independently (MLP=3) with ZERO extra bytes.
__global__ void k_gather(const float* __restrict__ X, int n) {
    int b = (blockIdx.x * blockDim.x + threadIdx.x) >> 5;
    if (b >= n * NREL) return;
    int lane = threadIdx.x & 31;
    int beg = g_off5[b], end = g_off5[b + 1];
    int node = b / NREL, rel = b - node * NREL;

    float ax = 0.f, ay = 0.f, az = 0.f, aw = 0.f;
    int e = beg;
    for (; e + 4 <= end; e += 4) {
        int s0 = __ldg(&g_edges[e]);
        int s1 = __ldg(&g_edges[e + 1]);
        int s2 = __ldg(&g_edges[e + 2]);
        int s3 = __ldg(&g_edges[e + 3]);
        float4 v0 = __ldg((const float4*)X + (size_t)s0 * 32 + lane);
        float4 v1 = __ldg((const float4*)X + (size_t)s1 * 32 + lane);
        float4 v2 = __ldg((const float4*)X + (size_t)s2 * 32 + lane);
        float4 v3 = __ldg((const float4*)X + (size_t)s3 * 32 + lane);
        ax += (v0.x + v1.x) + (v2.x + v3.x);
        ay += (v0.y + v1.y) + (v2.y + v3.y);
        az += (v0.z + v1.z) + (v2.z + v3.z);
        aw += (v0.w + v1.w) + (v2.w + v3.w);
    }
    // predicated remainder: independent loads, no clamping, no extra traffic
    {
        float4 v0 = make_float4(0.f, 0.f, 0.f, 0.f), v1 = v0, v2 = v0;
        if (e < end) {
            int s = __ldg(&g_edges[e]);
            v0 = __ldg((const float4*)X + (size_t)s * 32 + lane);
        }
        if (e + 1 < end) {
            int s = __ldg(&g_edges[e + 1]);
            v1 = __ldg((const float4*)X + (size_t)s * 32 + lane);
        }
        if (e + 2 < end) {
            int s = __ldg(&g_edges[e + 2]);
            v2 = __ldg((const float4*)X + (size_t)s * 32 + lane);
        }
        ax += (v0.x + v1.x) + v2.x;
        ay += (v0.y + v1.y) + v2.y;
        az += (v0.z + v1.z) + v2.z;
        aw += (v0.w + v1.w) + v2.w;
    }
    int cnt = end - beg;
    float sc = cnt ? 1.f / (float)cnt : 0.f;
    float f0 = ax * sc, f1 = ay * sc, f2 = az * sc, f3 = aw * sc;

    __nv_bfloat16 h0, l0, h1, l1, h2, l2, h3, l3;
    bsplit(f0, h0, l0); bsplit(f1, h1, l1);
    bsplit(f2, h2, l2); bsplit(f3, h3, l3);
    __nv_bfloat162 hA = __halves2bfloat162(h0, h1);
    __nv_bfloat162 hB = __halves2bfloat162(h2, h3);
    __nv_bfloat162 lA = __halves2bfloat162(l0, l1);
    __nv_bfloat162 lB = __halves2bfloat162(l2, l3);
    // contiguous 512B block per bucket: hi[256B] | lo[256B]
    unsigned char* base = g_AG + ((size_t)rel * NN_PAD + node) * 512;
    *(uint2*)(base + lane * 8)       = make_uint2(*(uint32_t*)&hA, *(uint32_t*)&hB);
    *(uint2*)(base + 256 + lane * 8) = make_uint2(*(uint32_t*)&lA, *(uint32_t*)&lB);
}

// ---------------- tcgen05 fused GEMM ----------------
// Y = relu([X | A0..A4] @ Bt + bias), 3-term bf16 split.
// 24 K-chunks of 32; SW64 tiles (128 rows x 64B); 3 stages of 32KB -> 2 CTAs/SM.
#define SMEM_TILES  1024
#define STAGE_BYTES 32768       // Ah(8K) Al(8K) Bh(8K) Bl(8K)
#define SMEM_TOTAL  (SMEM_TILES + 3 * STAGE_BYTES)
#define NCHUNK      24
#define MMA_IDESC   ((1u << 4) | (1u << 7) | (1u << 10) | (16u << 17) | (8u << 24))

#if HAS_TCGEN05
__device__ __forceinline__ uint64_t sdesc64(uint32_t a) {
    // SW64 (layout=4), version=1 (Blackwell), SBO=32, LBO=1 (K-major, 64B rows)
    return ((uint64_t)4 << 61) | ((uint64_t)1 << 46) | ((uint64_t)32 << 32) |
           ((uint64_t)1 << 16) | (uint64_t)((a >> 4) & 0x3FFF);
}
__device__ __forceinline__ void mma_f16_ss(uint32_t d, uint64_t ad, uint64_t bd,
                                           uint32_t idesc, uint32_t en) {
    asm volatile(
        "{\n\t.reg .pred p;\n\t"
        "setp.ne.u32 p, %4, 0;\n\t"
        "tcgen05.mma.cta_group::1.kind::f16 [%0], %1, %2, %3, {%5, %5, %5, %5}, p;\n\t}"
        :: "r"(d), "l"(ad), "l"(bd), "r"(idesc), "r"(en), "r"(0u) : "memory");
}
__device__ __forceinline__ void mma_commit(uint32_t mbar) {
    asm volatile(
        "tcgen05.commit.cta_group::1.mbarrier::arrive::one.shared::cluster.b64 [%0];"
        :: "r"(mbar) : "memory");
}
#define LDTM_X32(r, addr)                                                        \
    asm volatile(                                                                \
        "tcgen05.ld.sync.aligned.32x32b.x32.b32 "                                \
        "{%0, %1, %2, %3, %4, %5, %6, %7, "                                      \
        " %8, %9, %10, %11, %12, %13, %14, %15, "                                \
        " %16, %17, %18, %19, %20, %21, %22, %23, "                              \
        " %24, %25, %26, %27, %28, %29, %30, %31}, [%32];"                       \
        : "=r"((r)[0]),  "=r"((r)[1]),  "=r"((r)[2]),  "=r"((r)[3]),             \
          "=r"((r)[4]),  "=r"((r)[5]),  "=r"((r)[6]),  "=r"((r)[7]),             \
          "=r"((r)[8]),  "=r"((r)[9]),  "=r"((r)[10]), "=r"((r)[11]),            \
          "=r"((r)[12]), "=r"((r)[13]), "=r"((r)[14]), "=r"((r)[15]),            \
          "=r"((r)[16]), "=r"((r)[17]), "=r"((r)[18]), "=r"((r)[19]),            \
          "=r"((r)[20]), "=r"((r)[21]), "=r"((r)[22]), "=r"((r)[23]),            \
          "=r"((r)[24]), "=r"((r)[25]), "=r"((r)[26]), "=r"((r)[27]),            \
          "=r"((r)[28]), "=r"((r)[29]), "=r"((r)[30]), "=r"((r)[31])             \
        : "r"(addr))

// chunks 0..3: A from f32 X (LDG+split+STS), B via cp.async.
// chunks 4..23: A from AG: rel=(c-4)>>2, quarter=(c-4)&3. All tiles SW64.
__device__ __forceinline__ void load_chunk(
    int c, char* smem, uint32_t stageOff, int m0, int tid,
    const float* __restrict__ X,
    const __nv_bfloat16* __restrict__ Bh, const __nv_bfloat16* __restrict__ Bl, int n)
{
    uint32_t sbase = s2u(smem) + stageOff;
    if (c < 4) {
        // B tiles via cp.async: 2 tiles x 512 units of 16B = 1024 units, 4/thread
#pragma unroll
        for (int i = 0; i < 4; i++) {
            int idx = tid + i * 256;
            int q = idx >> 9, j = idx & 511;
            int row = j >> 2, s16 = j & 3;
            uint32_t byte = row * 64 + s16 * 16;
            uint32_t dstp = sbase + 16384 + q * 8192 + (byte ^ ((byte >> 3) & 0x30));
            const char* srcp = (const char*)(q ? Bl : Bh) + (size_t)row * 1536 + c * 64 + s16 * 16;
            asm volatile("cp.async.cg.shared.global [%0], [%1], 16;" :: "r"(dstp), "l"(srcp));
        }
        asm volatile("cp.async.commit_group;" ::: "memory");
        // A tiles: f32 X -> bf16 hi/lo split -> swizzled STS (16 cols per thread)
        int row = tid >> 1, h = tid & 1;
        int node = m0 + row;
        const float* xr = X + (size_t)node * 128 + c * 32 + h * 16;
#pragma unroll
        for (int j = 0; j < 2; j++) {
            float v[8];
            if (node < n) {
                float4 f0 = __ldg((const float4*)(xr + j * 8));
                float4 f1 = __ldg((const float4*)(xr + j * 8) + 1);
                v[0] = f0.x; v[1] = f0.y; v[2] = f0.z; v[3] = f0.w;
                v[4] = f1.x; v[5] = f1.y; v[6] = f1.z; v[7] = f1.w;
            } else {
#pragma unroll
                for (int q = 0; q < 8; q++) v[q] = 0.f;
            }
            uint4 hi, lo;
            pack8(v, hi, lo);
            uint32_t byte = row * 64 + h * 32 + j * 16;
            uint32_t sw = byte ^ ((byte >> 3) & 0x30);
            *(uint4*)(smem + stageOff + sw) = hi;
            *(uint4*)(smem + stageOff + 8192 + sw) = lo;
        }
    } else {
        int rc = (c - 4) >> 2;                 // relation 0..4
        int qr = (c - 4) & 3;                  // quarter: cols qr*32..qr*32+31
        const unsigned char* agbase =
            g_AG + ((size_t)rc * NN_PAD + m0) * 512 + qr * 64;
        // 4 tiles x 512 units = 2048 units, 8/thread
#pragma unroll
        for (int i = 0; i < 8; i++) {
            int idx = tid + i * 256;
            int sub = idx >> 9, j = idx & 511;
            int row = j >> 2, s16 = j & 3;
            uint32_t byte = row * 64 + s16 * 16;
            uint32_t dstp = sbase + sub * 8192 + (byte ^ ((byte >> 3) & 0x30));
            const char* srcp;
            if (sub == 0)      srcp = (const char*)agbase + (size_t)row * 512 + s16 * 16;
            else if (sub == 1) srcp = (const char*)agbase + (size_t)row * 512 + 256 + s16 * 16;
            else if (sub == 2) srcp = (const char*)Bh + (size_t)row * 1536 + c * 64 + s16 * 16;
            else               srcp = (const char*)Bl + (size_t)row * 1536 + c * 64 + s16 * 16;
            asm volatile("cp.async.cg.shared.global [%0], [%1], 16;" :: "r"(dstp), "l"(srcp));
        }
        asm volatile("cp.async.commit_group;" ::: "memory");
    }
}
#endif  // HAS_TCGEN05

__global__ void __launch_bounds__(256, 2) k_mma(
    const float* __restrict__ X,
    const __nv_bfloat16* __restrict__ Bh, const __nv_bfloat16* __restrict__ Bl,
    const float* __restrict__ bias, float* __restrict__ Y, int n)
{
#if HAS_TCGEN05
    extern __shared__ char smem[];
    uint32_t sb = s2u(smem);
    int tid = threadIdx.x;
    int wid = tid >> 5, lane = tid & 31;
    int m0 = blockIdx.x * 128;

    if (wid == 0) {
        asm volatile(
            "tcgen05.alloc.cta_group::1.sync.aligned.shared::cta.b32 [%0], %1;"
            :: "r"(sb), "r"(128u) : "memory");
        asm volatile("tcgen05.relinquish_alloc_permit.cta_group::1.sync.aligned;");
    }
    if (tid == 0) {
        mbar_init(sb + 16, 1);
        mbar_init(sb + 24, 1);
        mbar_init(sb + 32, 1);
    }
    __syncthreads();
    uint32_t tmem;
    asm volatile("ld.shared.b32 %0, [%1];" : "=r"(tmem) : "r"(sb));

    load_chunk(0, smem, SMEM_TILES + 0 * STAGE_BYTES, m0, tid, X, Bh, Bl, n);
    load_chunk(1, smem, SMEM_TILES + 1 * STAGE_BYTES, m0, tid, X, Bh, Bl, n);

#pragma unroll 4
    for (int c = 0; c < NCHUNK; c++) {
        // 1) chunk c's data ready
        if (c <= NCHUNK - 2) asm volatile("cp.async.wait_group 1;" ::: "memory");
        else                 asm volatile("cp.async.wait_group 0;" ::: "memory");
        __syncthreads();
        // 2) issue MMA c
        if (tid == 0) {
            asm volatile("fence.proxy.async.shared::cta;" ::: "memory");
            uint32_t tb = sb + SMEM_TILES + (c % 3) * STAGE_BYTES;
            uint64_t dAh = sdesc64(tb);
            uint64_t dAl = sdesc64(tb + 8192);
            uint64_t dBh = sdesc64(tb + 16384);
            uint64_t dBl = sdesc64(tb + 24576);
#pragma unroll
            for (int ks = 0; ks < 2; ks++) {
                uint32_t e0 = (c == 0 && ks == 0) ? 0u : 1u;
                mma_f16_ss(tmem, dAh + ks * 2, dBh + ks * 2, MMA_IDESC, e0);
                mma_f16_ss(tmem, dAh + ks * 2, dBl + ks * 2, MMA_IDESC, 1u);
                mma_f16_ss(tmem, dAl + ks * 2, dBh + ks * 2, MMA_IDESC, 1u);
            }
            mma_commit(sb + 16 + (c % 3) * 8);
        }
        // 3) wait MMA c-1 (frees buffer (c+2)%3)
        if (c >= 1) {
            int t = c - 1;
            mbar_wait(sb + 16 + (t % 3) * 8, (t / 3) & 1);
        }
        // 4) loads for chunk c+2
        if (c + 2 < NCHUNK)
            load_chunk(c + 2, smem, SMEM_TILES + ((c + 2) % 3) * STAGE_BYTES,
                       m0, tid, X, Bh, Bl, n);
    }
    // final: chunk 23 commit on mbar (23%3)=2 -> parity ((23/3)&1)=1
    mbar_wait(sb + 32, (((NCHUNK - 1) / 3) & 1));
    asm volatile("tcgen05.fence::after_thread_sync;" ::: "memory");

    // ---- epilogue: TMEM -> bias+relu -> SMEM transpose -> coalesced f32 stores ----
    float* smF = (float*)(smem + SMEM_TILES);   // [128][129] f32 (66KB, fits)
    int sp = wid & 3, hh = wid >> 2;
#pragma unroll
    for (int p = 0; p < 2; p++) {
        uint32_t r[32];
        LDTM_X32(r, tmem + hh * 64 + p * 32);
        asm volatile("tcgen05.wait::ld.sync.aligned;" ::: "memory");
        int cb = hh * 64 + p * 32;
#pragma unroll
        for (int j = 0; j < 32; j++) {
            float v = __uint_as_float(r[j]) + __ldg(&bias[cb + j]);
            smF[(sp * 32 + lane) * 129 + cb + j] = fmaxf(v, 0.f);
        }
    }
    __syncthreads();
    for (int idx = tid; idx < 4096; idx += 256) {
        int row = idx >> 5, q = idx & 31;
        int grow = m0 + row;
        if (grow < n) {
            float* s = &smF[row * 129 + q * 4];
            float4 o;
            o.x = s[0]; o.y = s[1]; o.z = s[2]; o.w = s[3];
            *(float4*)(Y + (size_t)grow * 128 + q * 4) = o;
        }
    }
    __syncthreads();
    if (wid == 0) {
        asm volatile(
            "tcgen05.dealloc.cta_group::1.sync.aligned.b32 %0, %1;"
            :: "r"(tmem), "r"(128u));
    }
#else
    // ---- fallback (family-generic PTX pass; never used when sm_103a SASS loads) ----
    int tid = threadIdx.x;
    int m0 = blockIdx.x * 128;
    for (int o = tid; o < 128 * 128; o += 256) {
        int row = m0 + (o >> 7), col = o & 127;
        if (row >= n) continue;
        float acc = bias[col];
        for (int k = 0; k < 128; k++) {
            float b = __bfloat162float(Bh[(size_t)col * KTOT + k]) +
                      __bfloat162float(Bl[(size_t)col * KTOT + k]);
            acc += X[(size_t)row * 128 + k] * b;
        }
        for (int r = 0; r < NREL; r++) {
            const unsigned char* base = g_AG + ((size_t)r * NN_PAD + row) * 512;
            const __nv_bfloat16* ph = (const __nv_bfloat16*)base;
            const __nv_bfloat16* pl = (const __nv_bfloat16*)(base + 256);
            for (int k = 0; k < 128; k++) {
                float a = __bfloat162float(ph[k]) + __bfloat162float(pl[k]);
                float b = __bfloat162float(Bh[(size_t)col * KTOT + 128 + r * 128 + k]) +
                          __bfloat162float(Bl[(size_t)col * KTOT + 128 + r * 128 + k]);
                acc += a * b;
            }
        }
        Y[(size_t)row * 128 + col] = fmaxf(acc, 0.f);
    }
#endif
}

// ---------------- launch ----------------
extern "C" void kernel_launch(void* const* d_in, const int* in_sizes, int n_in,
                              void* d_out, int out_size) {
    const float* x  = (const float*)d_in[0];
    const int*   ei = (const int*)d_in[1];
    const int*   et = (const int*)d_in[2];
    const float* W1 = (const float*)d_in[3];
    const float* r1 = (const float*)d_in[4];
    const float* b1 = (const float*)d_in[5];
    const float* W2 = (const float*)d_in[6];
    const float* r2 = (const float*)d_in[7];
    const float* b2 = (const float*)d_in[8];
    const float* W3 = (const float*)d_in[9];
    const float* r3 = (const float*)d_in[10];
    const float* b3 = (const float*)d_in[11];
    float* out = (float*)d_out;

    int n = in_sizes[0] / F;
    int E = in_sizes[1] / 2;
    const int* src = ei;
    const int* dst = ei + E;
    int m = n * NREL;

    float *pB1, *pB2;
    __nv_bfloat16 *pBh, *pBl;
    cudaGetSymbolAddress((void**)&pB1, g_B1);
    cudaGetSymbolAddress((void**)&pB2, g_B2);
    cudaGetSymbolAddress((void**)&pBh, g_Bh);
    cudaGetSymbolAddress((void**)&pBl, g_Bl);

    static int smem_set = 0;
    if (!smem_set) {
        cudaFuncSetAttribute(k_mma, cudaFuncAttributeMaxDynamicSharedMemorySize, SMEM_TOTAL);
        smem_set = 1;
    }

    int gb = (m * 32 + 255) / 256;       // one warp per (node, rel) bucket
    int mb = (n + 127) / 128;

    k_csr<<<CSR_NB, 1024>>>(src, dst, et, E, m);
    k_prepB<<<(3 * BLAYER + 255) / 256, 256>>>(W1, r1, W2, r2, W3, r3);
    // layer 1  (k_mma is 4th launch -> ncu capture target)
    k_gather<<<gb, 256>>>(x, n);
    k_mma<<<mb, 256, SMEM_TOTAL>>>(x, pBh, pBl, b1, pB1, n);
    // layer 2
    k_gather<<<gb, 256>>>(pB1, n);
    k_mma<<<mb, 256, SMEM_TOTAL>>>(pB1, pBh + BLAYER, pBl + BLAYER, b2, pB2, n);
    // layer 3
    k_gather<<<gb, 256>>>(pB2, n);
    k_mma<<<mb, 256, SMEM_TOTAL>>>(pB2, pBh + 2 * BLAYER, pBl + 2 * BLAYER, b3, out, n);
}

// round 14
// speedup vs baseline: 1.1367x; 1.0726x over previous
#include <cuda_runtime.h>
#include <cuda.h>
#include <cuda_bf16.h>
#include <cstdint>

#define NN      100000
#define NE      1600000
#define F       128
#define NREL    5
#define NN_PAD  100096          // 782 * 128
#define KTOT    768
#define BLAYER  98304           // 128 * 768 per-layer B elements
#define M5      (NN * NREL)
#define CSR_NB  120             // resident blocks for software grid sync

#if defined(__CUDA_ARCH_FEAT_SM103_ALL) || defined(__CUDA_ARCH_FEAT_SM100_ALL)
#define HAS_TCGEN05 1
#else
#define HAS_TCGEN05 0
#endif

// ---------------- device scratch (no allocations allowed) ----------------
// AG layout: [rel][node][512B block] = 128 bf16 hi (256B) then 128 bf16 lo (256B)
__device__ __align__(256) unsigned char g_AG[(size_t)NREL * NN_PAD * 512];
__device__ __align__(256) __nv_bfloat16 g_Bh[3 * BLAYER];   // weights hi [l][n][k]
__device__ __align__(256) __nv_bfloat16 g_Bl[3 * BLAYER];
__device__ float g_B1[(size_t)NN * F];
__device__ float g_B2[(size_t)NN * F];
__device__ int   g_deg5[M5];
__device__ int   g_off5[M5 + 1];
__device__ int   g_cur5[M5];
__device__ int   g_edges[NE];                 // src, sorted by (dst, rel)
__device__ int   g_bsums[512];
__device__ int   g_bar = 0;
__device__ volatile unsigned g_sense = 0;
__device__ __align__(64) CUtensorMap g_tmaAG;
__device__ __align__(64) CUtensorMap g_tmaBh;
__device__ __align__(64) CUtensorMap g_tmaBl;

// ---------------- small helpers ----------------
__device__ __forceinline__ uint32_t s2u(const void* p) {
    return (uint32_t)__cvta_generic_to_shared(p);
}
__device__ __forceinline__ void bsplit(float v, __nv_bfloat16& h, __nv_bfloat16& l) {
    h = __float2bfloat16_rn(v);
    l = __float2bfloat16_rn(v - __bfloat162float(h));
}
__device__ __forceinline__ void pack8(const float* f, uint4& hi, uint4& lo) {
    uint32_t h[4], l[4];
#pragma unroll
    for (int i = 0; i < 4; i++) {
        __nv_bfloat16 h0, l0, h1, l1;
        bsplit(f[2 * i], h0, l0);
        bsplit(f[2 * i + 1], h1, l1);
        __nv_bfloat162 hh = __halves2bfloat162(h0, h1);
        __nv_bfloat162 ll = __halves2bfloat162(l0, l1);
        h[i] = *(uint32_t*)&hh;
        l[i] = *(uint32_t*)&ll;
    }
    hi = make_uint4(h[0], h[1], h[2], h[3]);
    lo = make_uint4(l[0], l[1], l[2], l[3]);
}
__device__ __forceinline__ void mbar_init(uint32_t a, uint32_t cnt) {
    asm volatile("mbarrier.init.shared.b64 [%0], %1;" :: "r"(a), "r"(cnt) : "memory");
}
__device__ __forceinline__ void mbar_wait(uint32_t a, int par) {
    asm volatile(
        "{\n\t.reg .pred P;\n"
        "WL%=:\n\t"
        "mbarrier.try_wait.parity.acquire.cta.shared::cta.b64 P, [%0], %1, 0x989680;\n\t"
        "@P bra WD%=;\n\t"
        "bra WL%=;\n"
        "WD%=:\n\t}"
        :: "r"(a), "r"(par) : "memory");
}
__device__ __forceinline__ void gsync(int nb) {
    __syncthreads();
    if (threadIdx.x == 0) {
        unsigned s = g_sense;
        __threadfence();
        if (atomicAdd(&g_bar, 1) == nb - 1) {
            g_bar = 0;
            __threadfence();
            g_sense = s + 1;
        } else {
            while (g_sense == s) { }
        }
        __threadfence();
    }
    __syncthreads();
}

// ---------------- single-kernel CSR build: zero -> hist -> scan -> place ----------------
__global__ void __launch_bounds__(1024, 1) k_csr(
    const int* __restrict__ src, const int* __restrict__ dst,
    const int* __restrict__ et, int E, int m)
{
    const int NB = gridDim.x;
    int tid = threadIdx.x, bid = blockIdx.x;
    int gt = bid * 1024 + tid, gs = NB * 1024;
    __shared__ int sh[1024];

    for (int i = gt; i < m; i += gs) g_deg5[i] = 0;
    for (int r = 0; r < NREL; r++) {
        unsigned char* p = g_AG + ((size_t)r * NN_PAD + NN) * 512;
        size_t bytes = (size_t)(NN_PAD - NN) * 512;
        for (size_t i = (size_t)gt * 16; i + 16 <= bytes; i += (size_t)gs * 16)
            *(uint4*)(p + i) = make_uint4(0, 0, 0, 0);
    }
    gsync(NB);

    for (int e = gt; e < E; e += gs) atomicAdd(&g_deg5[dst[e] * NREL + et[e]], 1);
    gsync(NB);

    int RB = (m + NB - 1) / NB;
    int CH = (RB + 1023) / 1024;
    int base = bid * RB;
    int lim = min(base + RB, m);
    int i0 = base + tid * CH;
    int mysum = 0;
#pragma unroll 4
    for (int j = 0; j < CH; j++) {
        int i = i0 + j;
        if (i < lim) mysum += g_deg5[i];
    }
    sh[tid] = mysum;
    __syncthreads();
    for (int d = 1; d < 1024; d <<= 1) {
        int t = (tid >= d) ? sh[tid - d] : 0;
        __syncthreads();
        sh[tid] += t;
        __syncthreads();
    }
    if (tid == 1023) g_bsums[bid] = sh[1023];
    int myoff_local = sh[tid] - mysum;
    gsync(NB);

    if (bid == 0) {
        int v = (tid < NB) ? g_bsums[tid] : 0;
        sh[tid] = v;
        __syncthreads();
        for (int d = 1; d < 1024; d <<= 1) {
            int t = (tid >= d) ? sh[tid - d] : 0;
            __syncthreads();
            sh[tid] += t;
            __syncthreads();
        }
        if (tid < NB) g_bsums[tid] = sh[tid] - v;
    }
    gsync(NB);

    int run = g_bsums[bid] + myoff_local;
#pragma unroll 4
    for (int j = 0; j < CH; j++) {
        int i = i0 + j;
        if (i < lim) {
            g_off5[i] = run;
            g_cur5[i] = run;
            run += g_deg5[i];
        }
    }
    if (gt == 0) g_off5[m] = E;
    gsync(NB);

    for (int e = gt; e < E; e += gs) {
        int b = dst[e] * NREL + et[e];
        int pos = atomicAdd(&g_cur5[b], 1);
        g_edges[pos] = src[e];
    }
}

// ---------------- weights -> transposed bf16 hi/lo B matrices ----------------
__global__ void k_prepB(const float* __restrict__ W1, const float* __restrict__ r1,
                        const float* __restrict__ W2, const float* __restrict__ r2,
                        const float* __restrict__ W3, const float* __restrict__ r3) {
    int idx = blockIdx.x * blockDim.x + threadIdx.x;
    if (idx >= 3 * BLAYER) return;
    int l = idx / BLAYER;
    int rem = idx % BLAYER;
    int nn = rem / KTOT;
    int k = rem % KTOT;
    const float* Wl = (l == 0) ? W1 : ((l == 1) ? W2 : W3);
    const float* rl = (l == 0) ? r1 : ((l == 1) ? r2 : r3);
    float v = (k < 128) ? rl[k * 128 + nn] : Wl[(size_t)(k - 128) * 128 + nn];
    __nv_bfloat16 h, lo;
    bsplit(v, h, lo);
    g_Bh[idx] = h;
    g_Bl[idx] = lo;
}

// ---------------- gather: one warp per (node, rel) bucket (R10 proven form) ----------------
__global__ void k_gather(const float* __restrict__ X, int n) {
    int b = (blockIdx.x * blockDim.x + threadIdx.x) >> 5;
    if (b >= n * NREL) return;
    int lane = threadIdx.x & 31;
    int beg = g_off5[b], end = g_off5[b + 1];
    int node = b / NREL, rel = b - node * NREL;

    float ax = 0.f, ay = 0.f, az = 0.f, aw = 0.f;
    int e = beg;
    for (; e + 4 <= end; e += 4) {
        int s0 = __ldg(&g_edges[e]);
        int s1 = __ldg(&g_edges[e + 1]);
        int s2 = __ldg(&g_edges[e + 2]);
        int s3 = __ldg(&g_edges[e + 3]);
        float4 v0 = __ldg((const float4*)X + (size_t)s0 * 32 + lane);
        float4 v1 = __ldg((const float4*)X + (size_t)s1 * 32 + lane);
        float4 v2 = __ldg((const float4*)X + (size_t)s2 * 32 + lane);
        float4 v3 = __ldg((const float4*)X + (size_t)s3 * 32 + lane);
        ax += (v0.x + v1.x) + (v2.x + v3.x);
        ay += (v0.y + v1.y) + (v2.y + v3.y);
        az += (v0.z + v1.z) + (v2.z + v3.z);
        aw += (v0.w + v1.w) + (v2.w + v3.w);
    }
    for (; e < end; e++) {
        int s0 = __ldg(&g_edges[e]);
        float4 v0 = __ldg((const float4*)X + (size_t)s0 * 32 + lane);
        ax += v0.x; ay += v0.y; az += v0.z; aw += v0.w;
    }
    int cnt = end - beg;
    float sc = cnt ? 1.f / (float)cnt : 0.f;
    float f0 = ax * sc, f1 = ay * sc, f2 = az * sc, f3 = aw * sc;

    __nv_bfloat16 h0, l0, h1, l1, h2, l2, h3, l3;
    bsplit(f0, h0, l0); bsplit(f1, h1, l1);
    bsplit(f2, h2, l2); bsplit(f3, h3, l3);
    __nv_bfloat162 hA = __halves2bfloat162(h0, h1);
    __nv_bfloat162 hB = __halves2bfloat162(h2, h3);
    __nv_bfloat162 lA = __halves2bfloat162(l0, l1);
    __nv_bfloat162 lB = __halves2bfloat162(l2, l3);
    unsigned char* base = g_AG + ((size_t)rel * NN_PAD + node) * 512;
    *(uint2*)(base + lane * 8)       = make_uint2(*(uint32_t*)&hA, *(uint32_t*)&hB);
    *(uint2*)(base + 256 + lane * 8) = make_uint2(*(uint32_t*)&lA, *(uint32_t*)&lB);
}

// ---------------- tcgen05 fused GEMM with TMA operand loads ----------------
// Y = relu([X | A0..A4] @ Bt + bias), 3-term bf16 split.
// 24 K-chunks of 32; SW64 tiles (128 rows x 64B); 3 stages of 32KB -> 2 CTAs/SM.
// Chunks >=4: all four tiles (AGhi/AGlo/Bh/Bl) via TMA. Chunks 0..3: B via TMA,
// A from f32 X via LDG+bsplit+STS.
#define SMEM_TILES  1024
#define STAGE_BYTES 32768
#define SMEM_TOTAL  (SMEM_TILES + 3 * STAGE_BYTES)
#define NCHUNK      24
#define MMA_IDESC   ((1u << 4) | (1u << 7) | (1u << 10) | (16u << 17) | (8u << 24))

#if HAS_TCGEN05
__device__ __forceinline__ uint64_t sdesc64(uint32_t a) {
    // SW64 (layout=4), version=1 (Blackwell), SBO=32, LBO=1 (K-major, 64B rows)
    return ((uint64_t)4 << 61) | ((uint64_t)1 << 46) | ((uint64_t)32 << 32) |
           ((uint64_t)1 << 16) | (uint64_t)((a >> 4) & 0x3FFF);
}
__device__ __forceinline__ void mma_f16_ss(uint32_t d, uint64_t ad, uint64_t bd,
                                           uint32_t idesc, uint32_t en) {
    asm volatile(
        "{\n\t.reg .pred p;\n\t"
        "setp.ne.u32 p, %4, 0;\n\t"
        "tcgen05.mma.cta_group::1.kind::f16 [%0], %1, %2, %3, {%5, %5, %5, %5}, p;\n\t}"
        :: "r"(d), "l"(ad), "l"(bd), "r"(idesc), "r"(en), "r"(0u) : "memory");
}
__device__ __forceinline__ void mma_commit(uint32_t mbar) {
    asm volatile(
        "tcgen05.commit.cta_group::1.mbarrier::arrive::one.shared::cluster.b64 [%0];"
        :: "r"(mbar) : "memory");
}
__device__ __forceinline__ void tma3d(uint32_t dst, const CUtensorMap* m,
                                      int x, int y, int z, uint32_t bar) {
    asm volatile(
        "cp.async.bulk.tensor.3d.shared::cta.global.tile.mbarrier::complete_tx::bytes "
        "[%0], [%1, {%2, %3, %4}], [%5];"
        :: "r"(dst), "l"(m), "r"(x), "r"(y), "r"(z), "r"(bar) : "memory");
}
__device__ __forceinline__ void mbar_expect(uint32_t bar, uint32_t bytes) {
    asm volatile("mbarrier.arrive.expect_tx.shared.b64 _, [%0], %1;"
                 :: "r"(bar), "r"(bytes) : "memory");
}
#define LDTM_X32(r, addr)                                                        \
    asm volatile(                                                                \
        "tcgen05.ld.sync.aligned.32x32b.x32.b32 "                                \
        "{%0, %1, %2, %3, %4, %5, %6, %7, "                                      \
        " %8, %9, %10, %11, %12, %13, %14, %15, "                                \
        " %16, %17, %18, %19, %20, %21, %22, %23, "                              \
        " %24, %25, %26, %27, %28, %29, %30, %31}, [%32];"                       \
        : "=r"((r)[0]),  "=r"((r)[1]),  "=r"((r)[2]),  "=r"((r)[3]),             \
          "=r"((r)[4]),  "=r"((r)[5]),  "=r"((r)[6]),  "=r"((r)[7]),             \
          "=r"((r)[8]),  "=r"((r)[9]),  "=r"((r)[10]), "=r"((r)[11]),            \
          "=r"((r)[12]), "=r"((r)[13]), "=r"((r)[14]), "=r"((r)[15]),            \
          "=r"((r)[16]), "=r"((r)[17]), "=r"((r)[18]), "=r"((r)[19]),            \
          "=r"((r)[20]), "=r"((r)[21]), "=r"((r)[22]), "=r"((r)[23]),            \
          "=r"((r)[24]), "=r"((r)[25]), "=r"((r)[26]), "=r"((r)[27]),            \
          "=r"((r)[28]), "=r"((r)[29]), "=r"((r)[30]), "=r"((r)[31])             \
        : "r"(addr))

// issue all loads for chunk cc into stage s. TMA by tid0; X-chunks' A via STS by all.
__device__ __forceinline__ void issue_chunk(
    int cc, char* smem, int s, int m0, int tid, int layer,
    const float* __restrict__ X,
    const CUtensorMap* mAG, const CUtensorMap* mBh, const CUtensorMap* mBl, int n)
{
    uint32_t sbase = s2u(smem) + SMEM_TILES + s * STAGE_BYTES;
    uint32_t fullb = s2u(smem) + 40 + s * 8;
    if (tid == 0) {
        if (cc < 4) {
            mbar_expect(fullb, 16384u);
        } else {
            mbar_expect(fullb, 32768u);
            int rc = (cc - 4) >> 2, qr = (cc - 4) & 3;
            tma3d(sbase,        mAG, qr * 64,       m0, rc, fullb);
            tma3d(sbase + 8192, mAG, 256 + qr * 64, m0, rc, fullb);
        }
        tma3d(sbase + 16384, mBh, cc * 64, 0, layer, fullb);
        tma3d(sbase + 24576, mBl, cc * 64, 0, layer, fullb);
    }
    if (cc < 4) {
        int row = tid >> 1, h = tid & 1;
        int node = m0 + row;
        const float* xr = X + (size_t)node * 128 + cc * 32 + h * 16;
#pragma unroll
        for (int j = 0; j < 2; j++) {
            float v[8];
            if (node < n) {
                float4 f0 = __ldg((const float4*)(xr + j * 8));
                float4 f1 = __ldg((const float4*)(xr + j * 8) + 1);
                v[0] = f0.x; v[1] = f0.y; v[2] = f0.z; v[3] = f0.w;
                v[4] = f1.x; v[5] = f1.y; v[6] = f1.z; v[7] = f1.w;
            } else {
#pragma unroll
                for (int q = 0; q < 8; q++) v[q] = 0.f;
            }
            uint4 hi, lo;
            pack8(v, hi, lo);
            uint32_t byte = row * 64 + h * 32 + j * 16;
            uint32_t sw = byte ^ ((byte >> 3) & 0x30);
            char* stp = smem + SMEM_TILES + s * STAGE_BYTES;
            *(uint4*)(stp + sw) = hi;
            *(uint4*)(stp + 8192 + sw) = lo;
        }
    }
}
#endif  // HAS_TCGEN05

__global__ void __launch_bounds__(256, 2) k_mma(
    const float* __restrict__ X,
    const CUtensorMap* __restrict__ mAG,
    const CUtensorMap* __restrict__ mBh,
    const CUtensorMap* __restrict__ mBl,
    const float* __restrict__ bias, float* __restrict__ Y, int n, int layer)
{
#if HAS_TCGEN05
    extern __shared__ char smem[];
    uint32_t sb = s2u(smem);
    int tid = threadIdx.x;
    int wid = tid >> 5, lane = tid & 31;
    int m0 = blockIdx.x * 128;

    if (wid == 0) {
        asm volatile(
            "tcgen05.alloc.cta_group::1.sync.aligned.shared::cta.b32 [%0], %1;"
            :: "r"(sb), "r"(128u) : "memory");
        asm volatile("tcgen05.relinquish_alloc_permit.cta_group::1.sync.aligned;");
    }
    if (tid == 0) {
        mbar_init(sb + 16, 1);   // mma-complete, stage 0
        mbar_init(sb + 24, 1);   // stage 1
        mbar_init(sb + 32, 1);   // stage 2
        mbar_init(sb + 40, 1);   // tma-full, stage 0
        mbar_init(sb + 48, 1);   // stage 1
        mbar_init(sb + 56, 1);   // stage 2
    }
    __syncthreads();
    uint32_t tmem;
    asm volatile("ld.shared.b32 %0, [%1];" : "=r"(tmem) : "r"(sb));

    issue_chunk(0, smem, 0, m0, tid, layer, X, mAG, mBh, mBl, n);
    issue_chunk(1, smem, 1, m0, tid, layer, X, mAG, mBh, mBl, n);

#pragma unroll 4
    for (int c = 0; c < NCHUNK; c++) {
        // 1) wait chunk c's TMA data; __syncthreads also covers the STS A-path
        mbar_wait(sb + 40 + (c % 3) * 8, (c / 3) & 1);
        __syncthreads();
        // 2) issue MMA c
        if (tid == 0) {
            asm volatile("fence.proxy.async.shared::cta;" ::: "memory");
            uint32_t tb = sb + SMEM_TILES + (c % 3) * STAGE_BYTES;
            uint64_t dAh = sdesc64(tb);
            uint64_t dAl = sdesc64(tb + 8192);
            uint64_t dBh = sdesc64(tb + 16384);
            uint64_t dBl = sdesc64(tb + 24576);
#pragma unroll
            for (int ks = 0; ks < 2; ks++) {
                uint32_t e0 = (c == 0 && ks == 0) ? 0u : 1u;
                mma_f16_ss(tmem, dAh + ks * 2, dBh + ks * 2, MMA_IDESC, e0);
                mma_f16_ss(tmem, dAh + ks * 2, dBl + ks * 2, MMA_IDESC, 1u);
                mma_f16_ss(tmem, dAl + ks * 2, dBh + ks * 2, MMA_IDESC, 1u);
            }
            mma_commit(sb + 16 + (c % 3) * 8);
        }
        // 3) wait MMA c-1 (frees buffer (c+2)%3)
        if (c >= 1) {
            int t = c - 1;
            mbar_wait(sb + 16 + (t % 3) * 8, (t / 3) & 1);
        }
        // 4) issue loads for chunk c+2
        if (c + 2 < NCHUNK)
            issue_chunk(c + 2, smem, (c + 2) % 3, m0, tid, layer, X, mAG, mBh, mBl, n);
    }
    mbar_wait(sb + 32, (((NCHUNK - 1) / 3) & 1));
    asm volatile("tcgen05.fence::after_thread_sync;" ::: "memory");

    // ---- epilogue: TMEM -> bias+relu -> SMEM transpose -> coalesced f32 stores ----
    float* smF = (float*)(smem + SMEM_TILES);   // [128][129] f32
    int sp = wid & 3, hh = wid >> 2;
#pragma unroll
    for (int p = 0; p < 2; p++) {
        uint32_t r[32];
        LDTM_X32(r, tmem + hh * 64 + p * 32);
        asm volatile("tcgen05.wait::ld.sync.aligned;" ::: "memory");
        int cb = hh * 64 + p * 32;
#pragma unroll
        for (int j = 0; j < 32; j++) {
            float v = __uint_as_float(r[j]) + __ldg(&bias[cb + j]);
            smF[(sp * 32 + lane) * 129 + cb + j] = fmaxf(v, 0.f);
        }
    }
    __syncthreads();
    for (int idx = tid; idx < 4096; idx += 256) {
        int row = idx >> 5, q = idx & 31;
        int grow = m0 + row;
        if (grow < n) {
            float* s = &smF[row * 129 + q * 4];
            float4 o;
            o.x = s[0]; o.y = s[1]; o.z = s[2]; o.w = s[3];
            *(float4*)(Y + (size_t)grow * 128 + q * 4) = o;
        }
    }
    __syncthreads();
    if (wid == 0) {
        asm volatile(
            "tcgen05.dealloc.cta_group::1.sync.aligned.b32 %0, %1;"
            :: "r"(tmem), "r"(128u));
    }
#else
    // ---- fallback (family-generic PTX pass; never used when sm_103a SASS loads) ----
    int tid = threadIdx.x;
    int m0 = blockIdx.x * 128;
    const __nv_bfloat16* Bh = g_Bh + (size_t)layer * BLAYER;
    const __nv_bfloat16* Bl = g_Bl + (size_t)layer * BLAYER;
    for (int o = tid; o < 128 * 128; o += 256) {
        int row = m0 + (o >> 7), col = o & 127;
        if (row >= n) continue;
        float acc = bias[col];
        for (int k = 0; k < 128; k++) {
            float b = __bfloat162float(Bh[(size_t)col * KTOT + k]) +
                      __bfloat162float(Bl[(size_t)col * KTOT + k]);
            acc += X[(size_t)row * 128 + k] * b;
        }
        for (int r = 0; r < NREL; r++) {
            const unsigned char* base = g_AG + ((size_t)r * NN_PAD + row) * 512;
            const __nv_bfloat16* ph = (const __nv_bfloat16*)base;
            const __nv_bfloat16* pl = (const __nv_bfloat16*)(base + 256);
            for (int k = 0; k < 128; k++) {
                float a = __bfloat162float(ph[k]) + __bfloat162float(pl[k]);
                float b = __bfloat162float(Bh[(size_t)col * KTOT + 128 + r * 128 + k]) +
                          __bfloat162float(Bl[(size_t)col * KTOT + 128 + r * 128 + k]);
                acc += a * b;
            }
        }
        Y[(size_t)row * 128 + col] = fmaxf(acc, 0.f);
    }
#endif
}

// ---------------- launch ----------------
typedef CUresult (*PFN_tmap_encode)(
    CUtensorMap*, CUtensorMapDataType, cuuint32_t, void*,
    const cuuint64_t*, const cuuint64_t*, const cuuint32_t*, const cuuint32_t*,
    CUtensorMapInterleave, CUtensorMapSwizzle, CUtensorMapL2promotion,
    CUtensorMapFloatOOBfill);

extern "C" void kernel_launch(void* const* d_in, const int* in_sizes, int n_in,
                              void* d_out, int out_size) {
    const float* x  = (const float*)d_in[0];
    const int*   ei = (const int*)d_in[1];
    const int*   et = (const int*)d_in[2];
    const float* W1 = (const float*)d_in[3];
    const float* r1 = (const float*)d_in[4];
    const float* b1 = (const float*)d_in[5];
    const float* W2 = (const float*)d_in[6];
    const float* r2 = (const float*)d_in[7];
    const float* b2 = (const float*)d_in[8];
    const float* W3 = (const float*)d_in[9];
    const float* r3 = (const float*)d_in[10];
    const float* b3 = (const float*)d_in[11];
    float* out = (float*)d_out;

    int n = in_sizes[0] / F;
    int E = in_sizes[1] / 2;
    const int* src = ei;
    const int* dst = ei + E;
    int m = n * NREL;

    float *pB1, *pB2;
    cudaGetSymbolAddress((void**)&pB1, g_B1);
    cudaGetSymbolAddress((void**)&pB2, g_B2);

    static int inited = 0;
    if (!inited) {
        cudaFuncSetAttribute(k_mma, cudaFuncAttributeMaxDynamicSharedMemorySize, SMEM_TOTAL);
        // build TMA tensor maps once (device symbol addresses are stable)
        PFN_tmap_encode enc = nullptr;
        cudaDriverEntryPointQueryResult qres;
        cudaGetDriverEntryPoint("cuTensorMapEncodeTiled", (void**)&enc,
                                cudaEnableDefault, &qres);
        void *agp, *bhp, *blp;
        cudaGetSymbolAddress(&agp, g_AG);
        cudaGetSymbolAddress(&bhp, g_Bh);
        cudaGetSymbolAddress(&blp, g_Bl);
        CUtensorMap mAG, mBh, mBl;
        cuuint32_t es[3] = {1, 1, 1};
        {
            cuuint64_t dims[3] = {512, NN_PAD, NREL};
            cuuint64_t strd[2] = {512, (cuuint64_t)NN_PAD * 512};
            cuuint32_t box[3] = {64, 128, 1};
            enc(&mAG, CU_TENSOR_MAP_DATA_TYPE_UINT8, 3, agp, dims, strd, box, es,
                CU_TENSOR_MAP_INTERLEAVE_NONE, CU_TENSOR_MAP_SWIZZLE_64B,
                CU_TENSOR_MAP_L2_PROMOTION_L2_128B, CU_TENSOR_MAP_FLOAT_OOB_FILL_NONE);
        }
        {
            cuuint64_t dims[3] = {1536, 128, 3};
            cuuint64_t strd[2] = {1536, (cuuint64_t)1536 * 128};
            cuuint32_t box[3] = {64, 128, 1};
            enc(&mBh, CU_TENSOR_MAP_DATA_TYPE_UINT8, 3, bhp, dims, strd, box, es,
                CU_TENSOR_MAP_INTERLEAVE_NONE, CU_TENSOR_MAP_SWIZZLE_64B,
                CU_TENSOR_MAP_L2_PROMOTION_L2_128B, CU_TENSOR_MAP_FLOAT_OOB_FILL_NONE);
            enc(&mBl, CU_TENSOR_MAP_DATA_TYPE_UINT8, 3, blp, dims, strd, box, es,
                CU_TENSOR_MAP_INTERLEAVE_NONE, CU_TENSOR_MAP_SWIZZLE_64B,
                CU_TENSOR_MAP_L2_PROMOTION_L2_128B, CU_TENSOR_MAP_FLOAT_OOB_FILL_NONE);
        }
        cudaMemcpyToSymbol(g_tmaAG, &mAG, sizeof(CUtensorMap));
        cudaMemcpyToSymbol(g_tmaBh, &mBh, sizeof(CUtensorMap));
        cudaMemcpyToSymbol(g_tmaBl, &mBl, sizeof(CUtensorMap));
        inited = 1;
    }
    CUtensorMap *dAG, *dBh, *dBl;
    cudaGetSymbolAddress((void**)&dAG, g_tmaAG);
    cudaGetSymbolAddress((void**)&dBh, g_tmaBh);
    cudaGetSymbolAddress((void**)&dBl, g_tmaBl);

    int gb = (m * 32 + 255) / 256;       // one warp per (node, rel) bucket
    int mb = (n + 127) / 128;

    k_csr<<<CSR_NB, 1024>>>(src, dst, et, E, m);
    k_prepB<<<(3 * BLAYER + 255) / 256, 256>>>(W1, r1, W2, r2, W3, r3);
    // layer 1  (k_mma is 4th launch -> ncu capture target)
    k_gather<<<gb, 256>>>(x, n);
    k_mma<<<mb, 256, SMEM_TOTAL>>>(x, dAG, dBh, dBl, b1, pB1, n, 0);
    // layer 2
    k_gather<<<gb, 256>>>(pB1, n);
    k_mma<<<mb, 256, SMEM_TOTAL>>>(pB1, dAG, dBh, dBl, b2, pB2, n, 1);
    // layer 3
    k_gather<<<gb, 256>>>(pB2, n);
    k_mma<<<mb, 256, SMEM_TOTAL>>>(pB2, dAG, dBh, dBl, b3, out, n, 2);
}

// round 15
// speedup vs baseline: 1.2155x; 1.0694x over previous
#include <cuda_runtime.h>
#include <cuda_bf16.h>
#include <cstdint>

#define NN      100000
#define NE      1600000
#define F       128
#define NREL    5
#define NN_PAD  100096          // 782 * 128
#define KTOT    768
#define BLAYER  98304           // 128 * 768 per-layer B elements
#define M5      (NN * NREL)
#define CSR_NB  120             // resident blocks for software grid sync

#if defined(__CUDA_ARCH_FEAT_SM103_ALL) || defined(__CUDA_ARCH_FEAT_SM100_ALL)
#define HAS_TCGEN05 1
#else
#define HAS_TCGEN05 0
#endif

// ---------------- device scratch (no allocations allowed) ----------------
// AG layout: [rel][node][512B block] = 128 bf16 hi (256B) then 128 bf16 lo (256B)
__device__ __align__(256) unsigned char g_AG[(size_t)NREL * NN_PAD * 512];
__device__ __align__(256) __nv_bfloat16 g_Bh[3 * BLAYER];   // weights hi [l][n][k]
__device__ __align__(256) __nv_bfloat16 g_Bl[3 * BLAYER];
__device__ float g_B1[(size_t)NN * F];
__device__ float g_B2[(size_t)NN * F];
__device__ int   g_deg5[M5];
__device__ int   g_off5[M5 + 1];
__device__ int   g_cur5[M5];
__device__ int   g_edges[NE];                 // src, sorted by (dst, rel)
__device__ int   g_bsums[512];
__device__ int   g_bar = 0;
__device__ volatile unsigned g_sense = 0;

// ---------------- small helpers ----------------
__device__ __forceinline__ uint32_t s2u(const void* p) {
    return (uint32_t)__cvta_generic_to_shared(p);
}
__device__ __forceinline__ void bsplit(float v, __nv_bfloat16& h, __nv_bfloat16& l) {
    h = __float2bfloat16_rn(v);
    l = __float2bfloat16_rn(v - __bfloat162float(h));
}
__device__ __forceinline__ void pack8(const float* f, uint4& hi, uint4& lo) {
    uint32_t h[4], l[4];
#pragma unroll
    for (int i = 0; i < 4; i++) {
        __nv_bfloat16 h0, l0, h1, l1;
        bsplit(f[2 * i], h0, l0);
        bsplit(f[2 * i + 1], h1, l1);
        __nv_bfloat162 hh = __halves2bfloat162(h0, h1);
        __nv_bfloat162 ll = __halves2bfloat162(l0, l1);
        h[i] = *(uint32_t*)&hh;
        l[i] = *(uint32_t*)&ll;
    }
    hi = make_uint4(h[0], h[1], h[2], h[3]);
    lo = make_uint4(l[0], l[1], l[2], l[3]);
}
__device__ __forceinline__ void mbar_init(uint32_t a, uint32_t cnt) {
    asm volatile("mbarrier.init.shared.b64 [%0], %1;" :: "r"(a), "r"(cnt) : "memory");
}
__device__ __forceinline__ void mbar_wait(uint32_t a, int par) {
    asm volatile(
        "{\n\t.reg .pred P;\n"
        "WL%=:\n\t"
        "mbarrier.try_wait.parity.acquire.cta.shared::cta.b64 P, [%0], %1, 0x989680;\n\t"
        "@P bra WD%=;\n\t"
        "bra WL%=;\n"
        "WD%=:\n\t}"
        :: "r"(a), "r"(par) : "memory");
}
__device__ __forceinline__ void gsync(int nb) {
    __syncthreads();
    if (threadIdx.x == 0) {
        unsigned s = g_sense;
        __threadfence();
        if (atomicAdd(&g_bar, 1) == nb - 1) {
            g_bar = 0;
            __threadfence();
            g_sense = s + 1;
        } else {
            while (g_sense == s) { }
        }
        __threadfence();
    }
    __syncthreads();
}

// ---------------- single-kernel CSR build: zero -> hist -> scan -> place ----------------
__global__ void __launch_bounds__(1024, 1) k_csr(
    const int* __restrict__ src, const int* __restrict__ dst,
    const int* __restrict__ et, int E, int m)
{
    const int NB = gridDim.x;
    int tid = threadIdx.x, bid = blockIdx.x;
    int gt = bid * 1024 + tid, gs = NB * 1024;
    __shared__ int sh[1024];

    for (int i = gt; i < m; i += gs) g_deg5[i] = 0;
    for (int r = 0; r < NREL; r++) {
        unsigned char* p = g_AG + ((size_t)r * NN_PAD + NN) * 512;
        size_t bytes = (size_t)(NN_PAD - NN) * 512;
        for (size_t i = (size_t)gt * 16; i + 16 <= bytes; i += (size_t)gs * 16)
            *(uint4*)(p + i) = make_uint4(0, 0, 0, 0);
    }
    gsync(NB);

    for (int e = gt; e < E; e += gs) atomicAdd(&g_deg5[dst[e] * NREL + et[e]], 1);
    gsync(NB);

    int RB = (m + NB - 1) / NB;
    int CH = (RB + 1023) / 1024;
    int base = bid * RB;
    int lim = min(base + RB, m);
    int i0 = base + tid * CH;
    int mysum = 0;
#pragma unroll 4
    for (int j = 0; j < CH; j++) {
        int i = i0 + j;
        if (i < lim) mysum += g_deg5[i];
    }
    sh[tid] = mysum;
    __syncthreads();
    for (int d = 1; d < 1024; d <<= 1) {
        int t = (tid >= d) ? sh[tid - d] : 0;
        __syncthreads();
        sh[tid] += t;
        __syncthreads();
    }
    if (tid == 1023) g_bsums[bid] = sh[1023];
    int myoff_local = sh[tid] - mysum;
    gsync(NB);

    if (bid == 0) {
        int v = (tid < NB) ? g_bsums[tid] : 0;
        sh[tid] = v;
        __syncthreads();
        for (int d = 1; d < 1024; d <<= 1) {
            int t = (tid >= d) ? sh[tid - d] : 0;
            __syncthreads();
            sh[tid] += t;
            __syncthreads();
        }
        if (tid < NB) g_bsums[tid] = sh[tid] - v;
    }
    gsync(NB);

    int run = g_bsums[bid] + myoff_local;
#pragma unroll 4
    for (int j = 0; j < CH; j++) {
        int i = i0 + j;
        if (i < lim) {
            g_off5[i] = run;
            g_cur5[i] = run;
            run += g_deg5[i];
        }
    }
    if (gt == 0) g_off5[m] = E;
    gsync(NB);

    for (int e = gt; e < E; e += gs) {
        int b = dst[e] * NREL + et[e];
        int pos = atomicAdd(&g_cur5[b], 1);
        g_edges[pos] = src[e];
    }
}

// ---------------- weights -> transposed bf16 hi/lo B matrices ----------------
__global__ void k_prepB(const float* __restrict__ W1, const float* __restrict__ r1,
                        const float* __restrict__ W2, const float* __restrict__ r2,
                        const float* __restrict__ W3, const float* __restrict__ r3) {
    int idx = blockIdx.x * blockDim.x + threadIdx.x;
    if (idx >= 3 * BLAYER) return;
    int l = idx / BLAYER;
    int rem = idx % BLAYER;
    int nn = rem / KTOT;
    int k = rem % KTOT;
    const float* Wl = (l == 0) ? W1 : ((l == 1) ? W2 : W3);
    const float* rl = (l == 0) ? r1 : ((l == 1) ? r2 : r3);
    float v = (k < 128) ? rl[k * 128 + nn] : Wl[(size_t)(k - 128) * 128 + nn];
    __nv_bfloat16 h, lo;
    bsplit(v, h, lo);
    g_Bh[idx] = h;
    g_Bl[idx] = lo;
}

// ---------------- gather: HALF-WARP per (node, rel) bucket ----------------
// 16 lanes cover a 512B X row (2 float4 per lane per edge). Main loop: 2 edges
// per iteration (4 independent loads/lane); remainder <=1 edge at MLP 2.
// Same byte traffic and load count as one-bucket-per-warp; 2x bucket parallelism.
__global__ void k_gather(const float* __restrict__ X, int n) {
    int w = (blockIdx.x * blockDim.x + threadIdx.x) >> 5;
    int lane = threadIdx.x & 31;
    int half = lane >> 4, hl = lane & 15;
    int b = w * 2 + half;
    if (b >= n * NREL) return;
    int beg = g_off5[b], end = g_off5[b + 1];
    int node = b / NREL, rel = b - node * NREL;

    float4 a0 = make_float4(0.f, 0.f, 0.f, 0.f), a1 = a0;
    int e = beg;
    for (; e + 2 <= end; e += 2) {
        int s0 = __ldg(&g_edges[e]);
        int s1 = __ldg(&g_edges[e + 1]);
        const float4* x0 = (const float4*)X + (size_t)s0 * 32 + hl * 2;
        const float4* x1 = (const float4*)X + (size_t)s1 * 32 + hl * 2;
        float4 u0 = __ldg(x0), u1 = __ldg(x0 + 1);
        float4 v0 = __ldg(x1), v1 = __ldg(x1 + 1);
        a0.x += u0.x + v0.x; a0.y += u0.y + v0.y;
        a0.z += u0.z + v0.z; a0.w += u0.w + v0.w;
        a1.x += u1.x + v1.x; a1.y += u1.y + v1.y;
        a1.z += u1.z + v1.z; a1.w += u1.w + v1.w;
    }
    if (e < end) {
        int s0 = __ldg(&g_edges[e]);
        const float4* x0 = (const float4*)X + (size_t)s0 * 32 + hl * 2;
        float4 u0 = __ldg(x0), u1 = __ldg(x0 + 1);
        a0.x += u0.x; a0.y += u0.y; a0.z += u0.z; a0.w += u0.w;
        a1.x += u1.x; a1.y += u1.y; a1.z += u1.z; a1.w += u1.w;
    }
    int cnt = end - beg;
    float sc = cnt ? 1.f / (float)cnt : 0.f;
    float f[8] = {a0.x * sc, a0.y * sc, a0.z * sc, a0.w * sc,
                  a1.x * sc, a1.y * sc, a1.z * sc, a1.w * sc};
    uint4 hi, lo;
    pack8(f, hi, lo);
    unsigned char* base = g_AG + ((size_t)rel * NN_PAD + node) * 512;
    *(uint4*)(base + hl * 16)       = hi;
    *(uint4*)(base + 256 + hl * 16) = lo;
}

// ---------------- tcgen05 fused GEMM (R10 proven form) ----------------
// Y = relu([X | A0..A4] @ Bt + bias), 3-term bf16 split.
// 24 K-chunks of 32; SW64 tiles (128 rows x 64B); 3 stages of 32KB -> 2 CTAs/SM.
#define SMEM_TILES  1024
#define STAGE_BYTES 32768       // Ah(8K) Al(8K) Bh(8K) Bl(8K)
#define SMEM_TOTAL  (SMEM_TILES + 3 * STAGE_BYTES)
#define NCHUNK      24
#define MMA_IDESC   ((1u << 4) | (1u << 7) | (1u << 10) | (16u << 17) | (8u << 24))

#if HAS_TCGEN05
__device__ __forceinline__ uint64_t sdesc64(uint32_t a) {
    // SW64 (layout=4), version=1 (Blackwell), SBO=32, LBO=1 (K-major, 64B rows)
    return ((uint64_t)4 << 61) | ((uint64_t)1 << 46) | ((uint64_t)32 << 32) |
           ((uint64_t)1 << 16) | (uint64_t)((a >> 4) & 0x3FFF);
}
__device__ __forceinline__ void mma_f16_ss(uint32_t d, uint64_t ad, uint64_t bd,
                                           uint32_t idesc, uint32_t en) {
    asm volatile(
        "{\n\t.reg .pred p;\n\t"
        "setp.ne.u32 p, %4, 0;\n\t"
        "tcgen05.mma.cta_group::1.kind::f16 [%0], %1, %2, %3, {%5, %5, %5, %5}, p;\n\t}"
        :: "r"(d), "l"(ad), "l"(bd), "r"(idesc), "r"(en), "r"(0u) : "memory");
}
__device__ __forceinline__ void mma_commit(uint32_t mbar) {
    asm volatile(
        "tcgen05.commit.cta_group::1.mbarrier::arrive::one.shared::cluster.b64 [%0];"
        :: "r"(mbar) : "memory");
}
#define LDTM_X32(r, addr)                                                        \
    asm volatile(                                                                \
        "tcgen05.ld.sync.aligned.32x32b.x32.b32 "                                \
        "{%0, %1, %2, %3, %4, %5, %6, %7, "                                      \
        " %8, %9, %10, %11, %12, %13, %14, %15, "                                \
        " %16, %17, %18, %19, %20, %21, %22, %23, "                              \
        " %24, %25, %26, %27, %28, %29, %30, %31}, [%32];"                       \
        : "=r"((r)[0]),  "=r"((r)[1]),  "=r"((r)[2]),  "=r"((r)[3]),             \
          "=r"((r)[4]),  "=r"((r)[5]),  "=r"((r)[6]),  "=r"((r)[7]),             \
          "=r"((r)[8]),  "=r"((r)[9]),  "=r"((r)[10]), "=r"((r)[11]),            \
          "=r"((r)[12]), "=r"((r)[13]), "=r"((r)[14]), "=r"((r)[15]),            \
          "=r"((r)[16]), "=r"((r)[17]), "=r"((r)[18]), "=r"((r)[19]),            \
          "=r"((r)[20]), "=r"((r)[21]), "=r"((r)[22]), "=r"((r)[23]),            \
          "=r"((r)[24]), "=r"((r)[25]), "=r"((r)[26]), "=r"((r)[27]),            \
          "=r"((r)[28]), "=r"((r)[29]), "=r"((r)[30]), "=r"((r)[31])             \
        : "r"(addr))

// chunks 0..3: A from f32 X (LDG+split+STS), B via cp.async.
// chunks 4..23: A from AG: rel=(c-4)>>2, quarter=(c-4)&3. All tiles SW64.
__device__ __forceinline__ void load_chunk(
    int c, char* smem, uint32_t stageOff, int m0, int tid,
    const float* __restrict__ X,
    const __nv_bfloat16* __restrict__ Bh, const __nv_bfloat16* __restrict__ Bl, int n)
{
    uint32_t sbase = s2u(smem) + stageOff;
    if (c < 4) {
#pragma unroll
        for (int i = 0; i < 4; i++) {
            int idx = tid + i * 256;
            int q = idx >> 9, j = idx & 511;
            int row = j >> 2, s16 = j & 3;
            uint32_t byte = row * 64 + s16 * 16;
            uint32_t dstp = sbase + 16384 + q * 8192 + (byte ^ ((byte >> 3) & 0x30));
            const char* srcp = (const char*)(q ? Bl : Bh) + (size_t)row * 1536 + c * 64 + s16 * 16;
            asm volatile("cp.async.cg.shared.global [%0], [%1], 16;" :: "r"(dstp), "l"(srcp));
        }
        asm volatile("cp.async.commit_group;" ::: "memory");
        int row = tid >> 1, h = tid & 1;
        int node = m0 + row;
        const float* xr = X + (size_t)node * 128 + c * 32 + h * 16;
#pragma unroll
        for (int j = 0; j < 2; j++) {
            float v[8];
            if (node < n) {
                float4 f0 = __ldg((const float4*)(xr + j * 8));
                float4 f1 = __ldg((const float4*)(xr + j * 8) + 1);
                v[0] = f0.x; v[1] = f0.y; v[2] = f0.z; v[3] = f0.w;
                v[4] = f1.x; v[5] = f1.y; v[6] = f1.z; v[7] = f1.w;
            } else {
#pragma unroll
                for (int q = 0; q < 8; q++) v[q] = 0.f;
            }
            uint4 hi, lo;
            pack8(v, hi, lo);
            uint32_t byte = row * 64 + h * 32 + j * 16;
            uint32_t sw = byte ^ ((byte >> 3) & 0x30);
            *(uint4*)(smem + stageOff + sw) = hi;
            *(uint4*)(smem + stageOff + 8192 + sw) = lo;
        }
    } else {
        int rc = (c - 4) >> 2;                 // relation 0..4
        int qr = (c - 4) & 3;                  // quarter: cols qr*32..qr*32+31
        const unsigned char* agbase =
            g_AG + ((size_t)rc * NN_PAD + m0) * 512 + qr * 64;
#pragma unroll
        for (int i = 0; i < 8; i++) {
            int idx = tid + i * 256;
            int sub = idx >> 9, j = idx & 511;
            int row = j >> 2, s16 = j & 3;
            uint32_t byte = row * 64 + s16 * 16;
            uint32_t dstp = sbase + sub * 8192 + (byte ^ ((byte >> 3) & 0x30));
            const char* srcp;
            if (sub == 0)      srcp = (const char*)agbase + (size_t)row * 512 + s16 * 16;
            else if (sub == 1) srcp = (const char*)agbase + (size_t)row * 512 + 256 + s16 * 16;
            else if (sub == 2) srcp = (const char*)Bh + (size_t)row * 1536 + c * 64 + s16 * 16;
            else               srcp = (const char*)Bl + (size_t)row * 1536 + c * 64 + s16 * 16;
            asm volatile("cp.async.cg.shared.global [%0], [%1], 16;" :: "r"(dstp), "l"(srcp));
        }
        asm volatile("cp.async.commit_group;" ::: "memory");
    }
}
#endif  // HAS_TCGEN05

__global__ void __launch_bounds__(256, 2) k_mma(
    const float* __restrict__ X,
    const __nv_bfloat16* __restrict__ Bh, const __nv_bfloat16* __restrict__ Bl,
    const float* __restrict__ bias, float* __restrict__ Y, int n)
{
#if HAS_TCGEN05
    extern __shared__ char smem[];
    uint32_t sb = s2u(smem);
    int tid = threadIdx.x;
    int wid = tid >> 5, lane = tid & 31;
    int m0 = blockIdx.x * 128;

    if (wid == 0) {
        asm volatile(
            "tcgen05.alloc.cta_group::1.sync.aligned.shared::cta.b32 [%0], %1;"
            :: "r"(sb), "r"(128u) : "memory");
        asm volatile("tcgen05.relinquish_alloc_permit.cta_group::1.sync.aligned;");
    }
    if (tid == 0) {
        mbar_init(sb + 16, 1);
        mbar_init(sb + 24, 1);
        mbar_init(sb + 32, 1);
    }
    __syncthreads();
    uint32_t tmem;
    asm volatile("ld.shared.b32 %0, [%1];" : "=r"(tmem) : "r"(sb));

    load_chunk(0, smem, SMEM_TILES + 0 * STAGE_BYTES, m0, tid, X, Bh, Bl, n);
    load_chunk(1, smem, SMEM_TILES + 1 * STAGE_BYTES, m0, tid, X, Bh, Bl, n);

#pragma unroll 4
    for (int c = 0; c < NCHUNK; c++) {
        // 1) chunk c's data ready
        if (c <= NCHUNK - 2) asm volatile("cp.async.wait_group 1;" ::: "memory");
        else                 asm volatile("cp.async.wait_group 0;" ::: "memory");
        __syncthreads();
        // 2) issue MMA c
        if (tid == 0) {
            asm volatile("fence.proxy.async.shared::cta;" ::: "memory");
            uint32_t tb = sb + SMEM_TILES + (c % 3) * STAGE_BYTES;
            uint64_t dAh = sdesc64(tb);
            uint64_t dAl = sdesc64(tb + 8192);
            uint64_t dBh = sdesc64(tb + 16384);
            uint64_t dBl = sdesc64(tb + 24576);
#pragma unroll
            for (int ks = 0; ks < 2; ks++) {
                uint32_t e0 = (c == 0 && ks == 0) ? 0u : 1u;
                mma_f16_ss(tmem, dAh + ks * 2, dBh + ks * 2, MMA_IDESC, e0);
                mma_f16_ss(tmem, dAh + ks * 2, dBl + ks * 2, MMA_IDESC, 1u);
                mma_f16_ss(tmem, dAl + ks * 2, dBh + ks * 2, MMA_IDESC, 1u);
            }
            mma_commit(sb + 16 + (c % 3) * 8);
        }
        // 3) wait MMA c-1 (frees buffer (c+2)%3)
        if (c >= 1) {
            int t = c - 1;
            mbar_wait(sb + 16 + (t % 3) * 8, (t / 3) & 1);
        }
        // 4) loads for chunk c+2
        if (c + 2 < NCHUNK)
            load_chunk(c + 2, smem, SMEM_TILES + ((c + 2) % 3) * STAGE_BYTES,
                       m0, tid, X, Bh, Bl, n);
    }
    mbar_wait(sb + 32, (((NCHUNK - 1) / 3) & 1));
    asm volatile("tcgen05.fence::after_thread_sync;" ::: "memory");

    // ---- epilogue: TMEM -> bias+relu -> SMEM transpose -> coalesced f32 stores ----
    float* smF = (float*)(smem + SMEM_TILES);   // [128][129] f32
    int sp = wid & 3, hh = wid >> 2;
#pragma unroll
    for (int p = 0; p < 2; p++) {
        uint32_t r[32];
        LDTM_X32(r, tmem + hh * 64 + p * 32);
        asm volatile("tcgen05.wait::ld.sync.aligned;" ::: "memory");
        int cb = hh * 64 + p * 32;
#pragma unroll
        for (int j = 0; j < 32; j++) {
            float v = __uint_as_float(r[j]) + __ldg(&bias[cb + j]);
            smF[(sp * 32 + lane) * 129 + cb + j] = fmaxf(v, 0.f);
        }
    }
    __syncthreads();
    for (int idx = tid; idx < 4096; idx += 256) {
        int row = idx >> 5, q = idx & 31;
        int grow = m0 + row;
        if (grow < n) {
            float* s = &smF[row * 129 + q * 4];
            float4 o;
            o.x = s[0]; o.y = s[1]; o.z = s[2]; o.w = s[3];
            *(float4*)(Y + (size_t)grow * 128 + q * 4) = o;
        }
    }
    __syncthreads();
    if (wid == 0) {
        asm volatile(
            "tcgen05.dealloc.cta_group::1.sync.aligned.b32 %0, %1;"
            :: "r"(tmem), "r"(128u));
    }
#else
    // ---- fallback (family-generic PTX pass; never used when sm_103a SASS loads) ----
    int tid = threadIdx.x;
    int m0 = blockIdx.x * 128;
    for (int o = tid; o < 128 * 128; o += 256) {
        int row = m0 + (o >> 7), col = o & 127;
        if (row >= n) continue;
        float acc = bias[col];
        for (int k = 0; k < 128; k++) {
            float b = __bfloat162float(Bh[(size_t)col * KTOT + k]) +
                      __bfloat162float(Bl[(size_t)col * KTOT + k]);
            acc += X[(size_t)row * 128 + k] * b;
        }
        for (int r = 0; r < NREL; r++) {
            const unsigned char* base = g_AG + ((size_t)r * NN_PAD + row) * 512;
            const __nv_bfloat16* ph = (const __nv_bfloat16*)base;
            const __nv_bfloat16* pl = (const __nv_bfloat16*)(base + 256);
            for (int k = 0; k < 128; k++) {
                float a = __bfloat162float(ph[k]) + __bfloat162float(pl[k]);
                float b = __bfloat162float(Bh[(size_t)col * KTOT + 128 + r * 128 + k]) +
                          __bfloat162float(Bl[(size_t)col * KTOT + 128 + r * 128 + k]);
                acc += a * b;
            }
        }
        Y[(size_t)row * 128 + col] = fmaxf(acc, 0.f);
    }
#endif
}

// ---------------- launch ----------------
extern "C" void kernel_launch(void* const* d_in, const int* in_sizes, int n_in,
                              void* d_out, int out_size) {
    const float* x  = (const float*)d_in[0];
    const int*   ei = (const int*)d_in[1];
    const int*   et = (const int*)d_in[2];
    const float* W1 = (const float*)d_in[3];
    const float* r1 = (const float*)d_in[4];
    const float* b1 = (const float*)d_in[5];
    const float* W2 = (const float*)d_in[6];
    const float* r2 = (const float*)d_in[7];
    const float* b2 = (const float*)d_in[8];
    const float* W3 = (const float*)d_in[9];
    const float* r3 = (const float*)d_in[10];
    const float* b3 = (const float*)d_in[11];
    float* out = (float*)d_out;

    int n = in_sizes[0] / F;
    int E = in_sizes[1] / 2;
    const int* src = ei;
    const int* dst = ei + E;
    int m = n * NREL;

    float *pB1, *pB2;
    __nv_bfloat16 *pBh, *pBl;
    cudaGetSymbolAddress((void**)&pB1, g_B1);
    cudaGetSymbolAddress((void**)&pB2, g_B2);
    cudaGetSymbolAddress((void**)&pBh, g_Bh);
    cudaGetSymbolAddress((void**)&pBl, g_Bl);

    static int smem_set = 0;
    if (!smem_set) {
        cudaFuncSetAttribute(k_mma, cudaFuncAttributeMaxDynamicSharedMemorySize, SMEM_TOTAL);
        smem_set = 1;
    }

    int gb = (m * 16 + 255) / 256;       // HALF-warp per (node, rel) bucket
    int mb = (n + 127) / 128;

    k_csr<<<CSR_NB, 1024>>>(src, dst, et, E, m);
    k_prepB<<<(3 * BLAYER + 255) / 256, 256>>>(W1, r1, W2, r2, W3, r3);
    // layer 1  (k_mma is 4th launch -> ncu capture target)
    k_gather<<<gb, 256>>>(x, n);
    k_mma<<<mb, 256, SMEM_TOTAL>>>(x, pBh, pBl, b1, pB1, n);
    // layer 2
    k_gather<<<gb, 256>>>(pB1, n);
    k_mma<<<mb, 256, SMEM_TOTAL>>>(pB1, pBh + BLAYER, pBl + BLAYER, b2, pB2, n);
    // layer 3
    k_gather<<<gb, 256>>>(pB2, n);
    k_mma<<<mb, 256, SMEM_TOTAL>>>(pB2, pBh + 2 * BLAYER, pBl + 2 * BLAYER, b3, out, n);
}

// round 16
// speedup vs baseline: 1.2170x; 1.0012x over previous
#include <cuda_runtime.h>
#include <cuda_bf16.h>
#include <cstdint>

#define NN      100000
#define NE      1600000
#define F       128
#define NREL    5
#define NN_PAD  100096          // 782 * 128
#define KTOT    768
#define BLAYER  98304           // 128 * 768 per-layer B elements
#define M5      (NN * NREL)
#define CSR_NB  120             // resident blocks for software grid sync

#if defined(__CUDA_ARCH_FEAT_SM103_ALL) || defined(__CUDA_ARCH_FEAT_SM100_ALL)
#define HAS_TCGEN05 1
#else
#define HAS_TCGEN05 0
#endif

// ---------------- device scratch (no allocations allowed) ----------------
// AG layout: [rel][node][512B block] = 128 bf16 hi (256B) then 128 bf16 lo (256B)
__device__ __align__(256) unsigned char g_AG[(size_t)NREL * NN_PAD * 512];
__device__ __align__(256) __nv_bfloat16 g_Bh[3 * BLAYER];   // weights hi [l][n][k]
__device__ __align__(256) __nv_bfloat16 g_Bl[3 * BLAYER];
__device__ float g_B1[(size_t)NN * F];
__device__ float g_B2[(size_t)NN * F];
__device__ int   g_deg5[M5];
__device__ int   g_off5[M5 + 1];
__device__ int   g_cur5[M5];
__device__ int   g_edges[NE];                 // src, sorted by (dst, rel)
__device__ int   g_bsums[512];
__device__ int   g_bar = 0;
__device__ volatile unsigned g_sense = 0;

// ---------------- small helpers ----------------
__device__ __forceinline__ uint32_t s2u(const void* p) {
    return (uint32_t)__cvta_generic_to_shared(p);
}
__device__ __forceinline__ void bsplit(float v, __nv_bfloat16& h, __nv_bfloat16& l) {
    h = __float2bfloat16_rn(v);
    l = __float2bfloat16_rn(v - __bfloat162float(h));
}
__device__ __forceinline__ void pack8(const float* f, uint4& hi, uint4& lo) {
    uint32_t h[4], l[4];
#pragma unroll
    for (int i = 0; i < 4; i++) {
        __nv_bfloat16 h0, l0, h1, l1;
        bsplit(f[2 * i], h0, l0);
        bsplit(f[2 * i + 1], h1, l1);
        __nv_bfloat162 hh = __halves2bfloat162(h0, h1);
        __nv_bfloat162 ll = __halves2bfloat162(l0, l1);
        h[i] = *(uint32_t*)&hh;
        l[i] = *(uint32_t*)&ll;
    }
    hi = make_uint4(h[0], h[1], h[2], h[3]);
    lo = make_uint4(l[0], l[1], l[2], l[3]);
}
__device__ __forceinline__ void mbar_init(uint32_t a, uint32_t cnt) {
    asm volatile("mbarrier.init.shared.b64 [%0], %1;" :: "r"(a), "r"(cnt) : "memory");
}
__device__ __forceinline__ void mbar_wait(uint32_t a, int par) {
    asm volatile(
        "{\n\t.reg .pred P;\n"
        "WL%=:\n\t"
        "mbarrier.try_wait.parity.acquire.cta.shared::cta.b64 P, [%0], %1, 0x989680;\n\t"
        "@P bra WD%=;\n\t"
        "bra WL%=;\n"
        "WD%=:\n\t}"
        :: "r"(a), "r"(par) : "memory");
}
__device__ __forceinline__ void gsync(int nb) {
    __syncthreads();
    if (threadIdx.x == 0) {
        unsigned s = g_sense;
        __threadfence();
        if (atomicAdd(&g_bar, 1) == nb - 1) {
            g_bar = 0;
            __threadfence();
            g_sense = s + 1;
        } else {
            while (g_sense == s) { }
        }
        __threadfence();
    }
    __syncthreads();
}

// ---------------- single-kernel CSR build: zero -> hist -> scan -> place ----------------
__global__ void __launch_bounds__(1024, 1) k_csr(
    const int* __restrict__ src, const int* __restrict__ dst,
    const int* __restrict__ et, int E, int m)
{
    const int NB = gridDim.x;
    int tid = threadIdx.x, bid = blockIdx.x;
    int gt = bid * 1024 + tid, gs = NB * 1024;
    __shared__ int sh[1024];

    for (int i = gt; i < m; i += gs) g_deg5[i] = 0;
    for (int r = 0; r < NREL; r++) {
        unsigned char* p = g_AG + ((size_t)r * NN_PAD + NN) * 512;
        size_t bytes = (size_t)(NN_PAD - NN) * 512;
        for (size_t i = (size_t)gt * 16; i + 16 <= bytes; i += (size_t)gs * 16)
            *(uint4*)(p + i) = make_uint4(0, 0, 0, 0);
    }
    gsync(NB);

    for (int e = gt; e < E; e += gs) atomicAdd(&g_deg5[dst[e] * NREL + et[e]], 1);
    gsync(NB);

    int RB = (m + NB - 1) / NB;
    int CH = (RB + 1023) / 1024;
    int base = bid * RB;
    int lim = min(base + RB, m);
    int i0 = base + tid * CH;
    int mysum = 0;
#pragma unroll 4
    for (int j = 0; j < CH; j++) {
        int i = i0 + j;
        if (i < lim) mysum += g_deg5[i];
    }
    sh[tid] = mysum;
    __syncthreads();
    for (int d = 1; d < 1024; d <<= 1) {
        int t = (tid >= d) ? sh[tid - d] : 0;
        __syncthreads();
        sh[tid] += t;
        __syncthreads();
    }
    if (tid == 1023) g_bsums[bid] = sh[1023];
    int myoff_local = sh[tid] - mysum;
    gsync(NB);

    if (bid == 0) {
        int v = (tid < NB) ? g_bsums[tid] : 0;
        sh[tid] = v;
        __syncthreads();
        for (int d = 1; d < 1024; d <<= 1) {
            int t = (tid >= d) ? sh[tid - d] : 0;
            __syncthreads();
            sh[tid] += t;
            __syncthreads();
        }
        if (tid < NB) g_bsums[tid] = sh[tid] - v;
    }
    gsync(NB);

    int run = g_bsums[bid] + myoff_local;
#pragma unroll 4
    for (int j = 0; j < CH; j++) {
        int i = i0 + j;
        if (i < lim) {
            g_off5[i] = run;
            g_cur5[i] = run;
            run += g_deg5[i];
        }
    }
    if (gt == 0) g_off5[m] = E;
    gsync(NB);

    for (int e = gt; e < E; e += gs) {
        int b = dst[e] * NREL + et[e];
        int pos = atomicAdd(&g_cur5[b], 1);
        g_edges[pos] = src[e];
    }
}

// ---------------- weights -> transposed bf16 hi/lo B matrices ----------------
__global__ void k_prepB(const float* __restrict__ W1, const float* __restrict__ r1,
                        const float* __restrict__ W2, const float* __restrict__ r2,
                        const float* __restrict__ W3, const float* __restrict__ r3) {
    int idx = blockIdx.x * blockDim.x + threadIdx.x;
    if (idx >= 3 * BLAYER) return;
    int l = idx / BLAYER;
    int rem = idx % BLAYER;
    int nn = rem / KTOT;
    int k = rem % KTOT;
    const float* Wl = (l == 0) ? W1 : ((l == 1) ? W2 : W3);
    const float* rl = (l == 0) ? r1 : ((l == 1) ? r2 : r3);
    float v = (k < 128) ? rl[k * 128 + nn] : Wl[(size_t)(k - 128) * 128 + nn];
    __nv_bfloat16 h, lo;
    bsplit(v, h, lo);
    g_Bh[idx] = h;
    g_Bl[idx] = lo;
}

// ---------------- gather: QUARTER-WARP per (node, rel) bucket ----------------
// 8 lanes cover a 512B X row (4 float4 per lane per edge). Main loop: 2 edges
// per iteration (8 independent loads/lane); remainder 1 edge at MLP 4.
// Identical byte traffic to previous forms; 4x bucket parallelism per warp.
__global__ void k_gather(const float* __restrict__ X, int n) {
    int w = (blockIdx.x * blockDim.x + threadIdx.x) >> 5;
    int lane = threadIdx.x & 31;
    int quad = lane >> 3, hl = lane & 7;
    int b = w * 4 + quad;
    if (b >= n * NREL) return;
    int beg = g_off5[b], end = g_off5[b + 1];
    int node = b / NREL, rel = b - node * NREL;

    float4 a0 = make_float4(0.f, 0.f, 0.f, 0.f), a1 = a0, a2 = a0, a3 = a0;
    int e = beg;
    for (; e + 2 <= end; e += 2) {
        int s0 = __ldg(&g_edges[e]);
        int s1 = __ldg(&g_edges[e + 1]);
        const float4* x0 = (const float4*)X + (size_t)s0 * 32 + hl * 4;
        const float4* x1 = (const float4*)X + (size_t)s1 * 32 + hl * 4;
        float4 u0 = __ldg(x0),     u1 = __ldg(x0 + 1);
        float4 u2 = __ldg(x0 + 2), u3 = __ldg(x0 + 3);
        float4 v0 = __ldg(x1),     v1 = __ldg(x1 + 1);
        float4 v2 = __ldg(x1 + 2), v3 = __ldg(x1 + 3);
        a0.x += u0.x + v0.x; a0.y += u0.y + v0.y; a0.z += u0.z + v0.z; a0.w += u0.w + v0.w;
        a1.x += u1.x + v1.x; a1.y += u1.y + v1.y; a1.z += u1.z + v1.z; a1.w += u1.w + v1.w;
        a2.x += u2.x + v2.x; a2.y += u2.y + v2.y; a2.z += u2.z + v2.z; a2.w += u2.w + v2.w;
        a3.x += u3.x + v3.x; a3.y += u3.y + v3.y; a3.z += u3.z + v3.z; a3.w += u3.w + v3.w;
    }
    if (e < end) {
        int s0 = __ldg(&g_edges[e]);
        const float4* x0 = (const float4*)X + (size_t)s0 * 32 + hl * 4;
        float4 u0 = __ldg(x0),     u1 = __ldg(x0 + 1);
        float4 u2 = __ldg(x0 + 2), u3 = __ldg(x0 + 3);
        a0.x += u0.x; a0.y += u0.y; a0.z += u0.z; a0.w += u0.w;
        a1.x += u1.x; a1.y += u1.y; a1.z += u1.z; a1.w += u1.w;
        a2.x += u2.x; a2.y += u2.y; a2.z += u2.z; a2.w += u2.w;
        a3.x += u3.x; a3.y += u3.y; a3.z += u3.z; a3.w += u3.w;
    }
    int cnt = end - beg;
    float sc = cnt ? 1.f / (float)cnt : 0.f;
    float f[16] = {a0.x * sc, a0.y * sc, a0.z * sc, a0.w * sc,
                   a1.x * sc, a1.y * sc, a1.z * sc, a1.w * sc,
                   a2.x * sc, a2.y * sc, a2.z * sc, a2.w * sc,
                   a3.x * sc, a3.y * sc, a3.z * sc, a3.w * sc};
    uint4 hi0, lo0, hi1, lo1;
    pack8(f, hi0, lo0);
    pack8(f + 8, hi1, lo1);
    unsigned char* base = g_AG + ((size_t)rel * NN_PAD + node) * 512;
    *(uint4*)(base + hl * 32)        = hi0;
    *(uint4*)(base + hl * 32 + 16)   = hi1;
    *(uint4*)(base + 256 + hl * 32)      = lo0;
    *(uint4*)(base + 256 + hl * 32 + 16) = lo1;
}

// ---------------- tcgen05 fused GEMM (R10 proven form) ----------------
// Y = relu([X | A0..A4] @ Bt + bias), 3-term bf16 split.
// 24 K-chunks of 32; SW64 tiles (128 rows x 64B); 3 stages of 32KB -> 2 CTAs/SM.
#define SMEM_TILES  1024
#define STAGE_BYTES 32768       // Ah(8K) Al(8K) Bh(8K) Bl(8K)
#define SMEM_TOTAL  (SMEM_TILES + 3 * STAGE_BYTES)
#define NCHUNK      24
#define MMA_IDESC   ((1u << 4) | (1u << 7) | (1u << 10) | (16u << 17) | (8u << 24))

#if HAS_TCGEN05
__device__ __forceinline__ uint64_t sdesc64(uint32_t a) {
    // SW64 (layout=4), version=1 (Blackwell), SBO=32, LBO=1 (K-major, 64B rows)
    return ((uint64_t)4 << 61) | ((uint64_t)1 << 46) | ((uint64_t)32 << 32) |
           ((uint64_t)1 << 16) | (uint64_t)((a >> 4) & 0x3FFF);
}
__device__ __forceinline__ void mma_f16_ss(uint32_t d, uint64_t ad, uint64_t bd,
                                           uint32_t idesc, uint32_t en) {
    asm volatile(
        "{\n\t.reg .pred p;\n\t"
        "setp.ne.u32 p, %4, 0;\n\t"
        "tcgen05.mma.cta_group::1.kind::f16 [%0], %1, %2, %3, {%5, %5, %5, %5}, p;\n\t}"
        :: "r"(d), "l"(ad), "l"(bd), "r"(idesc), "r"(en), "r"(0u) : "memory");
}
__device__ __forceinline__ void mma_commit(uint32_t mbar) {
    asm volatile(
        "tcgen05.commit.cta_group::1.mbarrier::arrive::one.shared::cluster.b64 [%0];"
        :: "r"(mbar) : "memory");
}
#define LDTM_X32(r, addr)                                                        \
    asm volatile(                                                                \
        "tcgen05.ld.sync.aligned.32x32b.x32.b32 "                                \
        "{%0, %1, %2, %3, %4, %5, %6, %7, "                                      \
        " %8, %9, %10, %11, %12, %13, %14, %15, "                                \
        " %16, %17, %18, %19, %20, %21, %22, %23, "                              \
        " %24, %25, %26, %27, %28, %29, %30, %31}, [%32];"                       \
        : "=r"((r)[0]),  "=r"((r)[1]),  "=r"((r)[2]),  "=r"((r)[3]),             \
          "=r"((r)[4]),  "=r"((r)[5]),  "=r"((r)[6]),  "=r"((r)[7]),             \
          "=r"((r)[8]),  "=r"((r)[9]),  "=r"((r)[10]), "=r"((r)[11]),            \
          "=r"((r)[12]), "=r"((r)[13]), "=r"((r)[14]), "=r"((r)[15]),            \
          "=r"((r)[16]), "=r"((r)[17]), "=r"((r)[18]), "=r"((r)[19]),            \
          "=r"((r)[20]), "=r"((r)[21]), "=r"((r)[22]), "=r"((r)[23]),            \
          "=r"((r)[24]), "=r"((r)[25]), "=r"((r)[26]), "=r"((r)[27]),            \
          "=r"((r)[28]), "=r"((r)[29]), "=r"((r)[30]), "=r"((r)[31])             \
        : "r"(addr))

// chunks 0..3: A from f32 X (LDG+split+STS), B via cp.async.
// chunks 4..23: A from AG: rel=(c-4)>>2, quarter=(c-4)&3. All tiles SW64.
__device__ __forceinline__ void load_chunk(
    int c, char* smem, uint32_t stageOff, int m0, int tid,
    const float* __restrict__ X,
    const __nv_bfloat16* __restrict__ Bh, const __nv_bfloat16* __restrict__ Bl, int n)
{
    uint32_t sbase = s2u(smem) + stageOff;
    if (c < 4) {
#pragma unroll
        for (int i = 0; i < 4; i++) {
            int idx = tid + i * 256;
            int q = idx >> 9, j = idx & 511;
            int row = j >> 2, s16 = j & 3;
            uint32_t byte = row * 64 + s16 * 16;
            uint32_t dstp = sbase + 16384 + q * 8192 + (byte ^ ((byte >> 3) & 0x30));
            const char* srcp = (const char*)(q ? Bl : Bh) + (size_t)row * 1536 + c * 64 + s16 * 16;
            asm volatile("cp.async.cg.shared.global [%0], [%1], 16;" :: "r"(dstp), "l"(srcp));
        }
        asm volatile("cp.async.commit_group;" ::: "memory");
        int row = tid >> 1, h = tid & 1;
        int node = m0 + row;
        const float* xr = X + (size_t)node * 128 + c * 32 + h * 16;
#pragma unroll
        for (int j = 0; j < 2; j++) {
            float v[8];
            if (node < n) {
                float4 f0 = __ldg((const float4*)(xr + j * 8));
                float4 f1 = __ldg((const float4*)(xr + j * 8) + 1);
                v[0] = f0.x; v[1] = f0.y; v[2] = f0.z; v[3] = f0.w;
                v[4] = f1.x; v[5] = f1.y; v[6] = f1.z; v[7] = f1.w;
            } else {
#pragma unroll
                for (int q = 0; q < 8; q++) v[q] = 0.f;
            }
            uint4 hi, lo;
            pack8(v, hi, lo);
            uint32_t byte = row * 64 + h * 32 + j * 16;
            uint32_t sw = byte ^ ((byte >> 3) & 0x30);
            *(uint4*)(smem + stageOff + sw) = hi;
            *(uint4*)(smem + stageOff + 8192 + sw) = lo;
        }
    } else {
        int rc = (c - 4) >> 2;                 // relation 0..4
        int qr = (c - 4) & 3;                  // quarter: cols qr*32..qr*32+31
        const unsigned char* agbase =
            g_AG + ((size_t)rc * NN_PAD + m0) * 512 + qr * 64;
#pragma unroll
        for (int i = 0; i < 8; i++) {
            int idx = tid + i * 256;
            int sub = idx >> 9, j = idx & 511;
            int row = j >> 2, s16 = j & 3;
            uint32_t byte = row * 64 + s16 * 16;
            uint32_t dstp = sbase + sub * 8192 + (byte ^ ((byte >> 3) & 0x30));
            const char* srcp;
            if (sub == 0)      srcp = (const char*)agbase + (size_t)row * 512 + s16 * 16;
            else if (sub == 1) srcp = (const char*)agbase + (size_t)row * 512 + 256 + s16 * 16;
            else if (sub == 2) srcp = (const char*)Bh + (size_t)row * 1536 + c * 64 + s16 * 16;
            else               srcp = (const char*)Bl + (size_t)row * 1536 + c * 64 + s16 * 16;
            asm volatile("cp.async.cg.shared.global [%0], [%1], 16;" :: "r"(dstp), "l"(srcp));
        }
        asm volatile("cp.async.commit_group;" ::: "memory");
    }
}
#endif  // HAS_TCGEN05

__global__ void __launch_bounds__(256, 2) k_mma(
    const float* __restrict__ X,
    const __nv_bfloat16* __restrict__ Bh, const __nv_bfloat16* __restrict__ Bl,
    const float* __restrict__ bias, float* __restrict__ Y, int n)
{
#if HAS_TCGEN05
    extern __shared__ char smem[];
    uint32_t sb = s2u(smem);
    int tid = threadIdx.x;
    int wid = tid >> 5, lane = tid & 31;
    int m0 = blockIdx.x * 128;

    if (wid == 0) {
        asm volatile(
            "tcgen05.alloc.cta_group::1.sync.aligned.shared::cta.b32 [%0], %1;"
            :: "r"(sb), "r"(128u) : "memory");
        asm volatile("tcgen05.relinquish_alloc_permit.cta_group::1.sync.aligned;");
    }
    if (tid == 0) {
        mbar_init(sb + 16, 1);
        mbar_init(sb + 24, 1);
        mbar_init(sb + 32, 1);
    }
    __syncthreads();
    uint32_t tmem;
    asm volatile("ld.shared.b32 %0, [%1];" : "=r"(tmem) : "r"(sb));

    load_chunk(0, smem, SMEM_TILES + 0 * STAGE_BYTES, m0, tid, X, Bh, Bl, n);
    load_chunk(1, smem, SMEM_TILES + 1 * STAGE_BYTES, m0, tid, X, Bh, Bl, n);

#pragma unroll 4
    for (int c = 0; c < NCHUNK; c++) {
        // 1) chunk c's data ready
        if (c <= NCHUNK - 2) asm volatile("cp.async.wait_group 1;" ::: "memory");
        else                 asm volatile("cp.async.wait_group 0;" ::: "memory");
        __syncthreads();
        // 2) issue MMA c
        if (tid == 0) {
            asm volatile("fence.proxy.async.shared::cta;" ::: "memory");
            uint32_t tb = sb + SMEM_TILES + (c % 3) * STAGE_BYTES;
            uint64_t dAh = sdesc64(tb);
            uint64_t dAl = sdesc64(tb + 8192);
            uint64_t dBh = sdesc64(tb + 16384);
            uint64_t dBl = sdesc64(tb + 24576);
#pragma unroll
            for (int ks = 0; ks < 2; ks++) {
                uint32_t e0 = (c == 0 && ks == 0) ? 0u : 1u;
                mma_f16_ss(tmem, dAh + ks * 2, dBh + ks * 2, MMA_IDESC, e0);
                mma_f16_ss(tmem, dAh + ks * 2, dBl + ks * 2, MMA_IDESC, 1u);
                mma_f16_ss(tmem, dAl + ks * 2, dBh + ks * 2, MMA_IDESC, 1u);
            }
            mma_commit(sb + 16 + (c % 3) * 8);
        }
        // 3) wait MMA c-1 (frees buffer (c+2)%3)
        if (c >= 1) {
            int t = c - 1;
            mbar_wait(sb + 16 + (t % 3) * 8, (t / 3) & 1);
        }
        // 4) loads for chunk c+2
        if (c + 2 < NCHUNK)
            load_chunk(c + 2, smem, SMEM_TILES + ((c + 2) % 3) * STAGE_BYTES,
                       m0, tid, X, Bh, Bl, n);
    }
    mbar_wait(sb + 32, (((NCHUNK - 1) / 3) & 1));
    asm volatile("tcgen05.fence::after_thread_sync;" ::: "memory");

    // ---- epilogue: TMEM -> bias+relu -> SMEM transpose -> coalesced f32 stores ----
    float* smF = (float*)(smem + SMEM_TILES);   // [128][129] f32
    int sp = wid & 3, hh = wid >> 2;
#pragma unroll
    for (int p = 0; p < 2; p++) {
        uint32_t r[32];
        LDTM_X32(r, tmem + hh * 64 + p * 32);
        asm volatile("tcgen05.wait::ld.sync.aligned;" ::: "memory");
        int cb = hh * 64 + p * 32;
#pragma unroll
        for (int j = 0; j < 32; j++) {
            float v = __uint_as_float(r[j]) + __ldg(&bias[cb + j]);
            smF[(sp * 32 + lane) * 129 + cb + j] = fmaxf(v, 0.f);
        }
    }
    __syncthreads();
    for (int idx = tid; idx < 4096; idx += 256) {
        int row = idx >> 5, q = idx & 31;
        int grow = m0 + row;
        if (grow < n) {
            float* s = &smF[row * 129 + q * 4];
            float4 o;
            o.x = s[0]; o.y = s[1]; o.z = s[2]; o.w = s[3];
            *(float4*)(Y + (size_t)grow * 128 + q * 4) = o;
        }
    }
    __syncthreads();
    if (wid == 0) {
        asm volatile(
            "tcgen05.dealloc.cta_group::1.sync.aligned.b32 %0, %1;"
            :: "r"(tmem), "r"(128u));
    }
#else
    // ---- fallback (family-generic PTX pass; never used when sm_103a SASS loads) ----
    int tid = threadIdx.x;
    int m0 = blockIdx.x * 128;
    for (int o = tid; o < 128 * 128; o += 256) {
        int row = m0 + (o >> 7), col = o & 127;
        if (row >= n) continue;
        float acc = bias[col];
        for (int k = 0; k < 128; k++) {
            float b = __bfloat162float(Bh[(size_t)col * KTOT + k]) +
                      __bfloat162float(Bl[(size_t)col * KTOT + k]);
            acc += X[(size_t)row * 128 + k] * b;
        }
        for (int r = 0; r < NREL; r++) {
            const unsigned char* base = g_AG + ((size_t)r * NN_PAD + row) * 512;
            const __nv_bfloat16* ph = (const __nv_bfloat16*)base;
            const __nv_bfloat16* pl = (const __nv_bfloat16*)(base + 256);
            for (int k = 0; k < 128; k++) {
                float a = __bfloat162float(ph[k]) + __bfloat162float(pl[k]);
                float b = __bfloat162float(Bh[(size_t)col * KTOT + 128 + r * 128 + k]) +
                          __bfloat162float(Bl[(size_t)col * KTOT + 128 + r * 128 + k]);
                acc += a * b;
            }
        }
        Y[(size_t)row * 128 + col] = fmaxf(acc, 0.f);
    }
#endif
}

// ---------------- launch ----------------
extern "C" void kernel_launch(void* const* d_in, const int* in_sizes, int n_in,
                              void* d_out, int out_size) {
    const float* x  = (const float*)d_in[0];
    const int*   ei = (const int*)d_in[1];
    const int*   et = (const int*)d_in[2];
    const float* W1 = (const float*)d_in[3];
    const float* r1 = (const float*)d_in[4];
    const float* b1 = (const float*)d_in[5];
    const float* W2 = (const float*)d_in[6];
    const float* r2 = (const float*)d_in[7];
    const float* b2 = (const float*)d_in[8];
    const float* W3 = (const float*)d_in[9];
    const float* r3 = (const float*)d_in[10];
    const float* b3 = (const float*)d_in[11];
    float* out = (float*)d_out;

    int n = in_sizes[0] / F;
    int E = in_sizes[1] / 2;
    const int* src = ei;
    const int* dst = ei + E;
    int m = n * NREL;

    float *pB1, *pB2;
    __nv_bfloat16 *pBh, *pBl;
    cudaGetSymbolAddress((void**)&pB1, g_B1);
    cudaGetSymbolAddress((void**)&pB2, g_B2);
    cudaGetSymbolAddress((void**)&pBh, g_Bh);
    cudaGetSymbolAddress((void**)&pBl, g_Bl);

    static int smem_set = 0;
    if (!smem_set) {
        cudaFuncSetAttribute(k_mma, cudaFuncAttributeMaxDynamicSharedMemorySize, SMEM_TOTAL);
        smem_set = 1;
    }

    int gb = (m * 8 + 255) / 256;        // QUARTER-warp per (node, rel) bucket
    int mb = (n + 127) / 128;

    k_csr<<<CSR_NB, 1024>>>(src, dst, et, E, m);
    k_prepB<<<(3 * BLAYER + 255) / 256, 256>>>(W1, r1, W2, r2, W3, r3);
    // layer 1  (k_mma is 4th launch -> ncu capture target)
    k_gather<<<gb, 256>>>(x, n);
    k_mma<<<mb, 256, SMEM_TOTAL>>>(x, pBh, pBl, b1, pB1, n);
    // layer 2
    k_gather<<<gb, 256>>>(pB1, n);
    k_mma<<<mb, 256, SMEM_TOTAL>>>(pB1, pBh + BLAYER, pBl + BLAYER, b2, pB2, n);
    // layer 3
    k_gather<<<gb, 256>>>(pB2, n);
    k_mma<<<mb, 256, SMEM_TOTAL>>>(pB2, pBh + 2 * BLAYER, pBl + 2 * BLAYER, b3, out, n);
}

// round 17
// speedup vs baseline: 1.2603x; 1.0355x over previous
#include <cuda_runtime.h>
#include <cuda_bf16.h>
#include <cuda_fp16.h>
#include <cstdint>

#define NN      100000
#define NE      1600000
#define F       128
#define NREL    5
#define NN_PAD  100096          // 782 * 128
#define KTOT    768
#define BLAYER  98304           // 128 * 768 per-layer B elements
#define M5      (NN * NREL)
#define CSR_NB  120             // resident blocks for software grid sync

#if defined(__CUDA_ARCH_FEAT_SM103_ALL) || defined(__CUDA_ARCH_FEAT_SM100_ALL)
#define HAS_TCGEN05 1
#else
#define HAS_TCGEN05 0
#endif

// ---------------- device scratch (no allocations allowed) ----------------
// AG layout: [rel][node][512B block] = 128 bf16 hi (256B) then 128 bf16 lo (256B)
__device__ __align__(256) unsigned char g_AG[(size_t)NREL * NN_PAD * 512];
__device__ __align__(256) __half g_Xf16[(size_t)NN_PAD * 128];  // fp16 copy of current X
__device__ __align__(256) __nv_bfloat16 g_Bh[3 * BLAYER];   // weights hi [l][n][k]
__device__ __align__(256) __nv_bfloat16 g_Bl[3 * BLAYER];
__device__ float g_B1[(size_t)NN * F];
__device__ float g_B2[(size_t)NN * F];
__device__ int   g_deg5[M5];
__device__ int   g_off5[M5 + 1];
__device__ int   g_cur5[M5];
__device__ int   g_edges[NE];                 // src, sorted by (dst, rel)
__device__ int   g_bsums[512];
__device__ int   g_bar = 0;
__device__ volatile unsigned g_sense = 0;

// ---------------- small helpers ----------------
__device__ __forceinline__ uint32_t s2u(const void* p) {
    return (uint32_t)__cvta_generic_to_shared(p);
}
__device__ __forceinline__ void bsplit(float v, __nv_bfloat16& h, __nv_bfloat16& l) {
    h = __float2bfloat16_rn(v);
    l = __float2bfloat16_rn(v - __bfloat162float(h));
}
__device__ __forceinline__ void pack8(const float* f, uint4& hi, uint4& lo) {
    uint32_t h[4], l[4];
#pragma unroll
    for (int i = 0; i < 4; i++) {
        __nv_bfloat16 h0, l0, h1, l1;
        bsplit(f[2 * i], h0, l0);
        bsplit(f[2 * i + 1], h1, l1);
        __nv_bfloat162 hh = __halves2bfloat162(h0, h1);
        __nv_bfloat162 ll = __halves2bfloat162(l0, l1);
        h[i] = *(uint32_t*)&hh;
        l[i] = *(uint32_t*)&ll;
    }
    hi = make_uint4(h[0], h[1], h[2], h[3]);
    lo = make_uint4(l[0], l[1], l[2], l[3]);
}
__device__ __forceinline__ void addh8(float* a, uint4 u) {
    __half2* h = (__half2*)&u;
#pragma unroll
    for (int i = 0; i < 4; i++) {
        float2 f = __half22float2(h[i]);
        a[2 * i]     += f.x;
        a[2 * i + 1] += f.y;
    }
}
__device__ __forceinline__ void mbar_init(uint32_t a, uint32_t cnt) {
    asm volatile("mbarrier.init.shared.b64 [%0], %1;" :: "r"(a), "r"(cnt) : "memory");
}
__device__ __forceinline__ void mbar_wait(uint32_t a, int par) {
    asm volatile(
        "{\n\t.reg .pred P;\n"
        "WL%=:\n\t"
        "mbarrier.try_wait.parity.acquire.cta.shared::cta.b64 P, [%0], %1, 0x989680;\n\t"
        "@P bra WD%=;\n\t"
        "bra WL%=;\n"
        "WD%=:\n\t}"
        :: "r"(a), "r"(par) : "memory");
}
__device__ __forceinline__ void gsync(int nb) {
    __syncthreads();
    if (threadIdx.x == 0) {
        unsigned s = g_sense;
        __threadfence();
        if (atomicAdd(&g_bar, 1) == nb - 1) {
            g_bar = 0;
            __threadfence();
            g_sense = s + 1;
        } else {
            while (g_sense == s) { }
        }
        __threadfence();
    }
    __syncthreads();
}

// ---------------- single-kernel CSR build: zero -> hist -> scan -> place ----------------
__global__ void __launch_bounds__(1024, 1) k_csr(
    const int* __restrict__ src, const int* __restrict__ dst,
    const int* __restrict__ et, int E, int m)
{
    const int NB = gridDim.x;
    int tid = threadIdx.x, bid = blockIdx.x;
    int gt = bid * 1024 + tid, gs = NB * 1024;
    __shared__ int sh[1024];

    for (int i = gt; i < m; i += gs) g_deg5[i] = 0;
    for (int r = 0; r < NREL; r++) {
        unsigned char* p = g_AG + ((size_t)r * NN_PAD + NN) * 512;
        size_t bytes = (size_t)(NN_PAD - NN) * 512;
        for (size_t i = (size_t)gt * 16; i + 16 <= bytes; i += (size_t)gs * 16)
            *(uint4*)(p + i) = make_uint4(0, 0, 0, 0);
    }
    gsync(NB);

    for (int e = gt; e < E; e += gs) atomicAdd(&g_deg5[dst[e] * NREL + et[e]], 1);
    gsync(NB);

    int RB = (m + NB - 1) / NB;
    int CH = (RB + 1023) / 1024;
    int base = bid * RB;
    int lim = min(base + RB, m);
    int i0 = base + tid * CH;
    int mysum = 0;
#pragma unroll 4
    for (int j = 0; j < CH; j++) {
        int i = i0 + j;
        if (i < lim) mysum += g_deg5[i];
    }
    sh[tid] = mysum;
    __syncthreads();
    for (int d = 1; d < 1024; d <<= 1) {
        int t = (tid >= d) ? sh[tid - d] : 0;
        __syncthreads();
        sh[tid] += t;
        __syncthreads();
    }
    if (tid == 1023) g_bsums[bid] = sh[1023];
    int myoff_local = sh[tid] - mysum;
    gsync(NB);

    if (bid == 0) {
        int v = (tid < NB) ? g_bsums[tid] : 0;
        sh[tid] = v;
        __syncthreads();
        for (int d = 1; d < 1024; d <<= 1) {
            int t = (tid >= d) ? sh[tid - d] : 0;
            __syncthreads();
            sh[tid] += t;
            __syncthreads();
        }
        if (tid < NB) g_bsums[tid] = sh[tid] - v;
    }
    gsync(NB);

    int run = g_bsums[bid] + myoff_local;
#pragma unroll 4
    for (int j = 0; j < CH; j++) {
        int i = i0 + j;
        if (i < lim) {
            g_off5[i] = run;
            g_cur5[i] = run;
            run += g_deg5[i];
        }
    }
    if (gt == 0) g_off5[m] = E;
    gsync(NB);

    for (int e = gt; e < E; e += gs) {
        int b = dst[e] * NREL + et[e];
        int pos = atomicAdd(&g_cur5[b], 1);
        g_edges[pos] = src[e];
    }
}

// ---------------- weights -> transposed bf16 hi/lo B matrices ----------------
__global__ void k_prepB(const float* __restrict__ W1, const float* __restrict__ r1,
                        const float* __restrict__ W2, const float* __restrict__ r2,
                        const float* __restrict__ W3, const float* __restrict__ r3) {
    int idx = blockIdx.x * blockDim.x + threadIdx.x;
    if (idx >= 3 * BLAYER) return;
    int l = idx / BLAYER;
    int rem = idx % BLAYER;
    int nn = rem / KTOT;
    int k = rem % KTOT;
    const float* Wl = (l == 0) ? W1 : ((l == 1) ? W2 : W3);
    const float* rl = (l == 0) ? r1 : ((l == 1) ? r2 : r3);
    float v = (k < 128) ? rl[k * 128 + nn] : Wl[(size_t)(k - 128) * 128 + nn];
    __nv_bfloat16 h, lo;
    bsplit(v, h, lo);
    g_Bh[idx] = h;
    g_Bl[idx] = lo;
}

// ---------------- f32 X -> fp16 copy (layer 1) ----------------
__global__ void k_conv(const float* __restrict__ x, int n) {
    size_t i = (size_t)blockIdx.x * blockDim.x + threadIdx.x;   // 4 elems each
    if (i * 4 >= (size_t)n * F) return;
    float4 f = __ldg((const float4*)x + i);
    __half2 h0 = __floats2half2_rn(f.x, f.y);
    __half2 h1 = __floats2half2_rn(f.z, f.w);
    *(uint2*)(g_Xf16 + i * 4) = make_uint2(*(uint32_t*)&h0, *(uint32_t*)&h1);
}

// ---------------- gather: QUARTER-WARP per bucket, reads fp16 X copy ----------------
// 8 lanes cover a 256B fp16 row (2 uint4 per lane per edge). Main loop 2 edges
// per iteration (4 independent row loads/lane). Reads halve vs f32.
__global__ void k_gather(int n) {
    int w = (blockIdx.x * blockDim.x + threadIdx.x) >> 5;
    int lane = threadIdx.x & 31;
    int quad = lane >> 3, hl = lane & 7;
    int b = w * 4 + quad;
    if (b >= n * NREL) return;
    int beg = g_off5[b], end = g_off5[b + 1];
    int node = b / NREL, rel = b - node * NREL;

    float acc[16];
#pragma unroll
    for (int i = 0; i < 16; i++) acc[i] = 0.f;

    int e = beg;
    for (; e + 2 <= end; e += 2) {
        int s0 = __ldg(&g_edges[e]);
        int s1 = __ldg(&g_edges[e + 1]);
        const uint4* p0 = (const uint4*)(g_Xf16 + (size_t)s0 * 128 + hl * 16);
        const uint4* p1 = (const uint4*)(g_Xf16 + (size_t)s1 * 128 + hl * 16);
        uint4 u0 = __ldg(p0), u1 = __ldg(p0 + 1);
        uint4 v0 = __ldg(p1), v1 = __ldg(p1 + 1);
        addh8(acc, u0);     addh8(acc + 8, u1);
        addh8(acc, v0);     addh8(acc + 8, v1);
    }
    if (e < end) {
        int s0 = __ldg(&g_edges[e]);
        const uint4* p0 = (const uint4*)(g_Xf16 + (size_t)s0 * 128 + hl * 16);
        uint4 u0 = __ldg(p0), u1 = __ldg(p0 + 1);
        addh8(acc, u0);     addh8(acc + 8, u1);
    }
    int cnt = end - beg;
    float sc = cnt ? 1.f / (float)cnt : 0.f;
#pragma unroll
    for (int i = 0; i < 16; i++) acc[i] *= sc;

    uint4 hi0, lo0, hi1, lo1;
    pack8(acc, hi0, lo0);
    pack8(acc + 8, hi1, lo1);
    unsigned char* base = g_AG + ((size_t)rel * NN_PAD + node) * 512;
    *(uint4*)(base + hl * 32)            = hi0;
    *(uint4*)(base + hl * 32 + 16)       = hi1;
    *(uint4*)(base + 256 + hl * 32)      = lo0;
    *(uint4*)(base + 256 + hl * 32 + 16) = lo1;
}

// ---------------- tcgen05 fused GEMM (R10 proven form + fp16-copy epilogue) ----------------
// Y = relu([X | A0..A4] @ Bt + bias), 3-term bf16 split.
// 24 K-chunks of 32; SW64 tiles (128 rows x 64B); 3 stages of 32KB -> 2 CTAs/SM.
#define SMEM_TILES  1024
#define STAGE_BYTES 32768       // Ah(8K) Al(8K) Bh(8K) Bl(8K)
#define SMEM_TOTAL  (SMEM_TILES + 3 * STAGE_BYTES)
#define NCHUNK      24
#define MMA_IDESC   ((1u << 4) | (1u << 7) | (1u << 10) | (16u << 17) | (8u << 24))

#if HAS_TCGEN05
__device__ __forceinline__ uint64_t sdesc64(uint32_t a) {
    // SW64 (layout=4), version=1 (Blackwell), SBO=32, LBO=1 (K-major, 64B rows)
    return ((uint64_t)4 << 61) | ((uint64_t)1 << 46) | ((uint64_t)32 << 32) |
           ((uint64_t)1 << 16) | (uint64_t)((a >> 4) & 0x3FFF);
}
__device__ __forceinline__ void mma_f16_ss(uint32_t d, uint64_t ad, uint64_t bd,
                                           uint32_t idesc, uint32_t en) {
    asm volatile(
        "{\n\t.reg .pred p;\n\t"
        "setp.ne.u32 p, %4, 0;\n\t"
        "tcgen05.mma.cta_group::1.kind::f16 [%0], %1, %2, %3, {%5, %5, %5, %5}, p;\n\t}"
        :: "r"(d), "l"(ad), "l"(bd), "r"(idesc), "r"(en), "r"(0u) : "memory");
}
__device__ __forceinline__ void mma_commit(uint32_t mbar) {
    asm volatile(
        "tcgen05.commit.cta_group::1.mbarrier::arrive::one.shared::cluster.b64 [%0];"
        :: "r"(mbar) : "memory");
}
#define LDTM_X32(r, addr)                                                        \
    asm volatile(                                                                \
        "tcgen05.ld.sync.aligned.32x32b.x32.b32 "                                \
        "{%0, %1, %2, %3, %4, %5, %6, %7, "                                      \
        " %8, %9, %10, %11, %12, %13, %14, %15, "                                \
        " %16, %17, %18, %19, %20, %21, %22, %23, "                              \
        " %24, %25, %26, %27, %28, %29, %30, %31}, [%32];"                       \
        : "=r"((r)[0]),  "=r"((r)[1]),  "=r"((r)[2]),  "=r"((r)[3]),             \
          "=r"((r)[4]),  "=r"((r)[5]),  "=r"((r)[6]),  "=r"((r)[7]),             \
          "=r"((r)[8]),  "=r"((r)[9]),  "=r"((r)[10]), "=r"((r)[11]),            \
          "=r"((r)[12]), "=r"((r)[13]), "=r"((r)[14]), "=r"((r)[15]),            \
          "=r"((r)[16]), "=r"((r)[17]), "=r"((r)[18]), "=r"((r)[19]),            \
          "=r"((r)[20]), "=r"((r)[21]), "=r"((r)[22]), "=r"((r)[23]),            \
          "=r"((r)[24]), "=r"((r)[25]), "=r"((r)[26]), "=r"((r)[27]),            \
          "=r"((r)[28]), "=r"((r)[29]), "=r"((r)[30]), "=r"((r)[31])             \
        : "r"(addr))

// chunks 0..3: A from f32 X (LDG+split+STS), B via cp.async.
// chunks 4..23: A from AG: rel=(c-4)>>2, quarter=(c-4)&3. All tiles SW64.
__device__ __forceinline__ void load_chunk(
    int c, char* smem, uint32_t stageOff, int m0, int tid,
    const float* __restrict__ X,
    const __nv_bfloat16* __restrict__ Bh, const __nv_bfloat16* __restrict__ Bl, int n)
{
    uint32_t sbase = s2u(smem) + stageOff;
    if (c < 4) {
#pragma unroll
        for (int i = 0; i < 4; i++) {
            int idx = tid + i * 256;
            int q = idx >> 9, j = idx & 511;
            int row = j >> 2, s16 = j & 3;
            uint32_t byte = row * 64 + s16 * 16;
            uint32_t dstp = sbase + 16384 + q * 8192 + (byte ^ ((byte >> 3) & 0x30));
            const char* srcp = (const char*)(q ? Bl : Bh) + (size_t)row * 1536 + c * 64 + s16 * 16;
            asm volatile("cp.async.cg.shared.global [%0], [%1], 16;" :: "r"(dstp), "l"(srcp));
        }
        asm volatile("cp.async.commit_group;" ::: "memory");
        int row = tid >> 1, h = tid & 1;
        int node = m0 + row;
        const float* xr = X + (size_t)node * 128 + c * 32 + h * 16;
#pragma unroll
        for (int j = 0; j < 2; j++) {
            float v[8];
            if (node < n) {
                float4 f0 = __ldg((const float4*)(xr + j * 8));
                float4 f1 = __ldg((const float4*)(xr + j * 8) + 1);
                v[0] = f0.x; v[1] = f0.y; v[2] = f0.z; v[3] = f0.w;
                v[4] = f1.x; v[5] = f1.y; v[6] = f1.z; v[7] = f1.w;
            } else {
#pragma unroll
                for (int q = 0; q < 8; q++) v[q] = 0.f;
            }
            uint4 hi, lo;
            pack8(v, hi, lo);
            uint32_t byte = row * 64 + h * 32 + j * 16;
            uint32_t sw = byte ^ ((byte >> 3) & 0x30);
            *(uint4*)(smem + stageOff + sw) = hi;
            *(uint4*)(smem + stageOff + 8192 + sw) = lo;
        }
    } else {
        int rc = (c - 4) >> 2;                 // relation 0..4
        int qr = (c - 4) & 3;                  // quarter: cols qr*32..qr*32+31
        const unsigned char* agbase =
            g_AG + ((size_t)rc * NN_PAD + m0) * 512 + qr * 64;
#pragma unroll
        for (int i = 0; i < 8; i++) {
            int idx = tid + i * 256;
            int sub = idx >> 9, j = idx & 511;
            int row = j >> 2, s16 = j & 3;
            uint32_t byte = row * 64 + s16 * 16;
            uint32_t dstp = sbase + sub * 8192 + (byte ^ ((byte >> 3) & 0x30));
            const char* srcp;
            if (sub == 0)      srcp = (const char*)agbase + (size_t)row * 512 + s16 * 16;
            else if (sub == 1) srcp = (const char*)agbase + (size_t)row * 512 + 256 + s16 * 16;
            else if (sub == 2) srcp = (const char*)Bh + (size_t)row * 1536 + c * 64 + s16 * 16;
            else               srcp = (const char*)Bl + (size_t)row * 1536 + c * 64 + s16 * 16;
            asm volatile("cp.async.cg.shared.global [%0], [%1], 16;" :: "r"(dstp), "l"(srcp));
        }
        asm volatile("cp.async.commit_group;" ::: "memory");
    }
}
#endif  // HAS_TCGEN05

__global__ void __launch_bounds__(256, 2) k_mma(
    const float* __restrict__ X,
    const __nv_bfloat16* __restrict__ Bh, const __nv_bfloat16* __restrict__ Bl,
    const float* __restrict__ bias, float* __restrict__ Y,
    __half* __restrict__ Yf16, int n)
{
#if HAS_TCGEN05
    extern __shared__ char smem[];
    uint32_t sb = s2u(smem);
    int tid = threadIdx.x;
    int wid = tid >> 5, lane = tid & 31;
    int m0 = blockIdx.x * 128;

    if (wid == 0) {
        asm volatile(
            "tcgen05.alloc.cta_group::1.sync.aligned.shared::cta.b32 [%0], %1;"
            :: "r"(sb), "r"(128u) : "memory");
        asm volatile("tcgen05.relinquish_alloc_permit.cta_group::1.sync.aligned;");
    }
    if (tid == 0) {
        mbar_init(sb + 16, 1);
        mbar_init(sb + 24, 1);
        mbar_init(sb + 32, 1);
    }
    __syncthreads();
    uint32_t tmem;
    asm volatile("ld.shared.b32 %0, [%1];" : "=r"(tmem) : "r"(sb));

    load_chunk(0, smem, SMEM_TILES + 0 * STAGE_BYTES, m0, tid, X, Bh, Bl, n);
    load_chunk(1, smem, SMEM_TILES + 1 * STAGE_BYTES, m0, tid, X, Bh, Bl, n);

#pragma unroll 4
    for (int c = 0; c < NCHUNK; c++) {
        // 1) chunk c's data ready
        if (c <= NCHUNK - 2) asm volatile("cp.async.wait_group 1;" ::: "memory");
        else                 asm volatile("cp.async.wait_group 0;" ::: "memory");
        __syncthreads();
        // 2) issue MMA c
        if (tid == 0) {
            asm volatile("fence.proxy.async.shared::cta;" ::: "memory");
            uint32_t tb = sb + SMEM_TILES + (c % 3) * STAGE_BYTES;
            uint64_t dAh = sdesc64(tb);
            uint64_t dAl = sdesc64(tb + 8192);
            uint64_t dBh = sdesc64(tb + 16384);
            uint64_t dBl = sdesc64(tb + 24576);
#pragma unroll
            for (int ks = 0; ks < 2; ks++) {
                uint32_t e0 = (c == 0 && ks == 0) ? 0u : 1u;
                mma_f16_ss(tmem, dAh + ks * 2, dBh + ks * 2, MMA_IDESC, e0);
                mma_f16_ss(tmem, dAh + ks * 2, dBl + ks * 2, MMA_IDESC, 1u);
                mma_f16_ss(tmem, dAl + ks * 2, dBh + ks * 2, MMA_IDESC, 1u);
            }
            mma_commit(sb + 16 + (c % 3) * 8);
        }
        // 3) wait MMA c-1 (frees buffer (c+2)%3)
        if (c >= 1) {
            int t = c - 1;
            mbar_wait(sb + 16 + (t % 3) * 8, (t / 3) & 1);
        }
        // 4) loads for chunk c+2
        if (c + 2 < NCHUNK)
            load_chunk(c + 2, smem, SMEM_TILES + ((c + 2) % 3) * STAGE_BYTES,
                       m0, tid, X, Bh, Bl, n);
    }
    mbar_wait(sb + 32, (((NCHUNK - 1) / 3) & 1));
    asm volatile("tcgen05.fence::after_thread_sync;" ::: "memory");

    // ---- epilogue: TMEM -> bias+relu -> SMEM transpose -> f32 + fp16 stores ----
    float* smF = (float*)(smem + SMEM_TILES);   // [128][129] f32
    int sp = wid & 3, hh = wid >> 2;
#pragma unroll
    for (int p = 0; p < 2; p++) {
        uint32_t r[32];
        LDTM_X32(r, tmem + hh * 64 + p * 32);
        asm volatile("tcgen05.wait::ld.sync.aligned;" ::: "memory");
        int cb = hh * 64 + p * 32;
#pragma unroll
        for (int j = 0; j < 32; j++) {
            float v = __uint_as_float(r[j]) + __ldg(&bias[cb + j]);
            smF[(sp * 32 + lane) * 129 + cb + j] = fmaxf(v, 0.f);
        }
    }
    __syncthreads();
    for (int idx = tid; idx < 4096; idx += 256) {
        int row = idx >> 5, q = idx & 31;
        int grow = m0 + row;
        if (grow < n) {
            float* s = &smF[row * 129 + q * 4];
            float4 o;
            o.x = s[0]; o.y = s[1]; o.z = s[2]; o.w = s[3];
            *(float4*)(Y + (size_t)grow * 128 + q * 4) = o;
            if (Yf16) {
                __half2 h0 = __floats2half2_rn(o.x, o.y);
                __half2 h1 = __floats2half2_rn(o.z, o.w);
                *(uint2*)(Yf16 + (size_t)grow * 128 + q * 4) =
                    make_uint2(*(uint32_t*)&h0, *(uint32_t*)&h1);
            }
        }
    }
    __syncthreads();
    if (wid == 0) {
        asm volatile(
            "tcgen05.dealloc.cta_group::1.sync.aligned.b32 %0, %1;"
            :: "r"(tmem), "r"(128u));
    }
#else
    // ---- fallback (family-generic PTX pass; never used when sm_103a SASS loads) ----
    int tid = threadIdx.x;
    int m0 = blockIdx.x * 128;
    for (int o = tid; o < 128 * 128; o += 256) {
        int row = m0 + (o >> 7), col = o & 127;
        if (row >= n) continue;
        float acc = bias[col];
        for (int k = 0; k < 128; k++) {
            float b = __bfloat162float(Bh[(size_t)col * KTOT + k]) +
                      __bfloat162float(Bl[(size_t)col * KTOT + k]);
            acc += X[(size_t)row * 128 + k] * b;
        }
        for (int r = 0; r < NREL; r++) {
            const unsigned char* base = g_AG + ((size_t)r * NN_PAD + row) * 512;
            const __nv_bfloat16* ph = (const __nv_bfloat16*)base;
            const __nv_bfloat16* pl = (const __nv_bfloat16*)(base + 256);
            for (int k = 0; k < 128; k++) {
                float a = __bfloat162float(ph[k]) + __bfloat162float(pl[k]);
                float b = __bfloat162float(Bh[(size_t)col * KTOT + 128 + r * 128 + k]) +
                          __bfloat162float(Bl[(size_t)col * KTOT + 128 + r * 128 + k]);
                acc += a * b;
            }
        }
        float v = fmaxf(acc, 0.f);
        Y[(size_t)row * 128 + col] = v;
        if (Yf16) Yf16[(size_t)row * 128 + col] = __float2half_rn(v);
    }
#endif
}

// ---------------- launch ----------------
extern "C" void kernel_launch(void* const* d_in, const int* in_sizes, int n_in,
                              void* d_out, int out_size) {
    const float* x  = (const float*)d_in[0];
    const int*   ei = (const int*)d_in[1];
    const int*   et = (const int*)d_in[2];
    const float* W1 = (const float*)d_in[3];
    const float* r1 = (const float*)d_in[4];
    const float* b1 = (const float*)d_in[5];
    const float* W2 = (const float*)d_in[6];
    const float* r2 = (const float*)d_in[7];
    const float* b2 = (const float*)d_in[8];
    const float* W3 = (const float*)d_in[9];
    const float* r3 = (const float*)d_in[10];
    const float* b3 = (const float*)d_in[11];
    float* out = (float*)d_out;

    int n = in_sizes[0] / F;
    int E = in_sizes[1] / 2;
    const int* src = ei;
    const int* dst = ei + E;
    int m = n * NREL;

    float *pB1, *pB2;
    __nv_bfloat16 *pBh, *pBl;
    __half *pXf;
    cudaGetSymbolAddress((void**)&pB1, g_B1);
    cudaGetSymbolAddress((void**)&pB2, g_B2);
    cudaGetSymbolAddress((void**)&pBh, g_Bh);
    cudaGetSymbolAddress((void**)&pBl, g_Bl);
    cudaGetSymbolAddress((void**)&pXf, g_Xf16);

    static int smem_set = 0;
    if (!smem_set) {
        cudaFuncSetAttribute(k_mma, cudaFuncAttributeMaxDynamicSharedMemorySize, SMEM_TOTAL);
        smem_set = 1;
    }

    int gb = (m * 8 + 255) / 256;        // QUARTER-warp per (node, rel) bucket
    int mb = (n + 127) / 128;
    int cb = (int)(((size_t)n * F / 4 + 255) / 256);

    k_csr<<<CSR_NB, 1024>>>(src, dst, et, E, m);
    k_prepB<<<(3 * BLAYER + 255) / 256, 256>>>(W1, r1, W2, r2, W3, r3);
    k_conv<<<cb, 256>>>(x, n);
    // layer 1
    k_gather<<<gb, 256>>>(n);
    k_mma<<<mb, 256, SMEM_TOTAL>>>(x, pBh, pBl, b1, pB1, pXf, n);
    // layer 2  (gather reads layer-1 fp16 copy written by previous mma)
    k_gather<<<gb, 256>>>(n);
    k_mma<<<mb, 256, SMEM_TOTAL>>>(pB1, pBh + BLAYER, pBl + BLAYER, b2, pB2, pXf, n);
    // layer 3
    k_gather<<<gb, 256>>>(n);
    k_mma<<<mb, 256, SMEM_TOTAL>>>(pB2, pBh + 2 * BLAYER, pBl + 2 * BLAYER, b3, out,
                                   (__half*)nullptr, n);
}